// round 8
// baseline (speedup 1.0000x reference)
#include <cuda_runtime.h>
#include <cuda_bf16.h>
#include <cstdint>
#include <cstddef>

#define M_MSG 131072
#define NNODE 65536
#define HID   256
#define DEPTH 6
#define NTREE 2048
#define GRID_P 148

#if defined(__CUDA_ARCH_FEAT_SM103_ALL) || defined(__CUDA_ARCH_FEAT_SM100_ALL) || \
    defined(__CUDA_ARCH_FEAT_SM101_ALL) || defined(__CUDA_ARCH_FEAT_SM110_ALL)
#define TC_OK 1
#else
#define TC_OK 0
#endif

// ---------------- static device scratch ------------------------------------
__device__ float g_U [(size_t)M_MSG * HID];       // Uh = h @ Ur
__device__ float g_h [(size_t)M_MSG * HID];       // h fp32 (gather consumer)
__device__ float g_zb[(size_t)M_MSG * HID];       // z gate
__device__ float g_t1[(size_t)M_MSG * HID];       // (1-z)*sum_h
__device__ float g_nv[(size_t)NNODE * HID];       // node_vec
__device__ float g_EX[780 * 768];                 // emb@[Wzx|Whx|Wr]+[bz|bh|Urb]
__device__ float g_EO[780 * 256];                 // emb@Ow1+Ob
__device__ int   g_mx[M_MSG];                     // fnode[fmess[m]]
// bf16 hi/lo split tensors (GEMM A operands)
__device__ __nv_bfloat16 g_hh [(size_t)M_MSG * HID], g_hl [(size_t)M_MSG * HID];
__device__ __nv_bfloat16 g_shh[(size_t)M_MSG * HID], g_shl[(size_t)M_MSG * HID]; // sum_h
__device__ __nv_bfloat16 g_sgh[(size_t)M_MSG * HID], g_sgl[(size_t)M_MSG * HID]; // sum_gh
__device__ __nv_bfloat16 g_mnh[(size_t)NNODE * HID], g_mnl[(size_t)NNODE * HID]; // mess_nei
// bf16 hi/lo split weights, [n][k] layout (B operand = W^T), all 256x256
__device__ __nv_bfloat16 g_BUh[256 * 256], g_BUl[256 * 256];   // Ur^T
__device__ __nv_bfloat16 g_BZh[256 * 256], g_BZl[256 * 256];   // Wzh^T
__device__ __nv_bfloat16 g_BHh[256 * 256], g_BHl[256 * 256];   // Whh^T
__device__ __nv_bfloat16 g_BOh[256 * 256], g_BOl[256 * 256];   // Ow2^T

// ---------------- PTX helpers ----------------------------------------------
__device__ __forceinline__ uint32_t su32(const void* p) {
    uint32_t a;
    asm("{ .reg .u64 t; cvta.to.shared.u64 t, %1; cvt.u32.u64 %0, t; }"
        : "=r"(a) : "l"(p));
    return a;
}
#if TC_OK
__device__ __forceinline__ bool elect1() {
    uint32_t p;
    asm volatile("{\n\t.reg .pred p;\n\telect.sync _|p, 0xFFFFFFFF;\n\t"
                 "selp.b32 %0, 1, 0, p;\n\t}" : "=r"(p));
    return p != 0;
}
__device__ __forceinline__ void mbar_init(uint32_t a, uint32_t cnt) {
    asm volatile("mbarrier.init.shared.b64 [%0], %1;" :: "r"(a), "r"(cnt) : "memory");
}
__device__ __forceinline__ void mbar_wait(uint32_t a, int par) {
    asm volatile(
        "{\n\t.reg .pred P;\n"
        "W%=:\n\t"
        "mbarrier.try_wait.parity.acquire.cta.shared::cta.b64 P, [%0], %1, 0x989680;\n\t"
        "@P bra.uni D%=;\n\t"
        "bra.uni W%=;\n"
        "D%=:\n\t}" :: "r"(a), "r"(par) : "memory");
}
__device__ __forceinline__ void tc_alloc(uint32_t smem_res, uint32_t ncols) {
    asm volatile("tcgen05.alloc.cta_group::1.sync.aligned.shared::cta.b32 [%0], %1;"
                 :: "r"(smem_res), "r"(ncols) : "memory");
}
__device__ __forceinline__ void tc_dealloc(uint32_t tmem, uint32_t ncols) {
    asm volatile("tcgen05.dealloc.cta_group::1.sync.aligned.b32 %0, %1;"
                 :: "r"(tmem), "r"(ncols));
}
__device__ __forceinline__ void tc_commit(uint32_t mbar) {
    asm volatile("tcgen05.commit.cta_group::1.mbarrier::arrive::one.shared::cluster.b64 [%0];"
                 :: "r"(mbar) : "memory");
}
__device__ __forceinline__ void mma_f16_ss(uint32_t d, uint64_t ad, uint64_t bd,
                                           uint32_t idesc, bool acc) {
    uint32_t en = acc ? 1u : 0u;
    asm volatile(
        "{\n\t.reg .pred p;\n\tsetp.ne.u32 p, %5, 0;\n\t"
        "tcgen05.mma.cta_group::1.kind::f16 [%0], %1, %2, %3, {%4, %4, %4, %4}, p;\n\t}"
        :: "r"(d), "l"(ad), "l"(bd), "r"(idesc), "r"(0u), "r"(en) : "memory");
}
__device__ __forceinline__ void tmem_ld32(uint32_t* r, uint32_t addr) {
    asm volatile(
        "tcgen05.ld.sync.aligned.32x32b.x32.b32 "
        "{%0,%1,%2,%3,%4,%5,%6,%7,%8,%9,%10,%11,%12,%13,%14,%15,"
        "%16,%17,%18,%19,%20,%21,%22,%23,%24,%25,%26,%27,%28,%29,%30,%31}, [%32];"
        : "=r"(r[0]), "=r"(r[1]), "=r"(r[2]), "=r"(r[3]),
          "=r"(r[4]), "=r"(r[5]), "=r"(r[6]), "=r"(r[7]),
          "=r"(r[8]), "=r"(r[9]), "=r"(r[10]), "=r"(r[11]),
          "=r"(r[12]), "=r"(r[13]), "=r"(r[14]), "=r"(r[15]),
          "=r"(r[16]), "=r"(r[17]), "=r"(r[18]), "=r"(r[19]),
          "=r"(r[20]), "=r"(r[21]), "=r"(r[22]), "=r"(r[23]),
          "=r"(r[24]), "=r"(r[25]), "=r"(r[26]), "=r"(r[27]),
          "=r"(r[28]), "=r"(r[29]), "=r"(r[30]), "=r"(r[31])
        : "r"(addr));
}
#define TC_WAIT_LD()     asm volatile("tcgen05.wait::ld.sync.aligned;" ::: "memory")
#define TC_FENCE_AFTER() asm volatile("tcgen05.fence::after_thread_sync;" ::: "memory")
#define TC_FENCE_BEFORE() asm volatile("tcgen05.fence::before_thread_sync;" ::: "memory")
#define FENCE_ASYNC()    asm volatile("fence.proxy.async.shared::cta;" ::: "memory")
#endif  // TC_OK

#define SWZ(o) ((o) ^ (((o) >> 3) & 0x70))

__device__ __forceinline__ uint64_t mk_desc(uint32_t addr) {
    return (2ull << 61) | (1ull << 46) | (64ull << 32) | (1ull << 16)
         | ((uint64_t)(addr >> 4) & 0x3FFF);
}

// idesc: dtype=F32, a=BF16, b=BF16, N=256, M=128
static constexpr uint32_t IDESC =
    (1u << 4) | (1u << 7) | (1u << 10) | ((256u / 8) << 17) | ((128u / 16) << 24);

// SMEM layout (bytes from 1024-aligned base)
#define OFF_PTR   0
#define OFF_MB    16          // mbar chunk[2]@16,24  tile[2]@32,40
#define OFF_TILE  1024
#define OFF_A(s, t) (OFF_TILE + (s) * 98304 + (t) * 16384)
#define OFF_B(s, t) (OFF_TILE + (s) * 98304 + 32768 + (t) * 32768)
#define TG_SMEM   (OFF_TILE + 2 * 98304 + 1024)   // 198656

// ---------------- helpers ----------------------------------------------
__device__ __forceinline__ float sgm(float x) { return 1.0f / (1.0f + __expf(-x)); }

__device__ __forceinline__ void bsplit(float w, __nv_bfloat16* H, __nv_bfloat16* L, size_t i) {
    __nv_bfloat16 h = __float2bfloat16(w);
    H[i] = h;
    L[i] = __float2bfloat16(w - __bfloat162float(h));
}
__device__ __forceinline__ uint32_t pk2(float a, float b) {
    return (uint32_t)__bfloat16_as_ushort(__float2bfloat16(a))
         | ((uint32_t)__bfloat16_as_ushort(__float2bfloat16(b)) << 16);
}
__device__ __forceinline__ float lo_of(float v) {
    return v - __bfloat162float(__float2bfloat16(v));
}

__global__ void k_zero2(float* h, __nv_bfloat16* hh, __nv_bfloat16* hl, int n) {
    int i = blockIdx.x * blockDim.x + threadIdx.x;
    if (i < n) { h[i] = 0.f; hh[i] = __float2bfloat16(0.f); hl[i] = __float2bfloat16(0.f); }
}

__global__ void k_pack(const float* __restrict__ Wz, const float* __restrict__ Wh,
                       const float* __restrict__ Ur, const float* __restrict__ Ow,
                       const int* __restrict__ fnode, const int* __restrict__ fmess,
                       int* __restrict__ mx) {
    int i = blockIdx.x * blockDim.x + threadIdx.x;
    int st = gridDim.x * blockDim.x;
    for (int t = i; t < 256 * 256; t += st) {
        int n = t >> 8, k = t & 255;
        bsplit(Ur[k * 256 + n],         g_BUh, g_BUl, t);
        bsplit(Wz[(256 + k) * 256 + n], g_BZh, g_BZl, t);
        bsplit(Wh[(256 + k) * 256 + n], g_BHh, g_BHl, t);
        bsplit(Ow[(256 + k) * 256 + n], g_BOh, g_BOl, t);
    }
    for (int t = i; t < M_MSG; t += st) mx[t] = fnode[fmess[t]];
}

// EX/EO tables: per-vocab precompute of all x-dependent matmuls.
__global__ void k_prep(const float* __restrict__ emb,
                       const float* __restrict__ Wz, const float* __restrict__ Wh,
                       const float* __restrict__ Wr, const float* __restrict__ Ow,
                       const float* __restrict__ Wzb, const float* __restrict__ Whb,
                       const float* __restrict__ Urb, const float* __restrict__ Ob,
                       float* __restrict__ EX, float* __restrict__ EO) {
    __shared__ float e[256];
    int v = blockIdx.x, j = threadIdx.x;
    e[j] = emb[v * 256 + j];
    __syncthreads();
    float s0 = 0, s1 = 0, s2 = 0, s3 = 0;
#pragma unroll 4
    for (int k = 0; k < 256; k++) {
        float ek = e[k];
        s0 = fmaf(ek, Wz[k * 256 + j], s0);
        s1 = fmaf(ek, Wh[k * 256 + j], s1);
        s2 = fmaf(ek, Wr[k * 256 + j], s2);
        s3 = fmaf(ek, Ow[k * 256 + j], s3);
    }
    EX[v * 768 + j]       = s0 + Wzb[j];
    EX[v * 768 + 256 + j] = s1 + Whb[j];
    EX[v * 768 + 512 + j] = s2 + Urb[j];
    EO[v * 256 + j]       = s3 + Ob[j];
}

// Per-message neighbor gather: sum_h, sum_gh (both emitted as bf16 hi/lo splits).
__global__ void k_gather(const int* __restrict__ mg, const float* __restrict__ h,
                         const float* __restrict__ U, const float* __restrict__ EX,
                         const int* __restrict__ mx,
                         __nv_bfloat16* __restrict__ shh, __nv_bfloat16* __restrict__ shl,
                         __nv_bfloat16* __restrict__ sgh, __nv_bfloat16* __restrict__ sgl) {
    int gt = blockIdx.x * blockDim.x + threadIdx.x;
    int msg = gt >> 6;
    int j = gt & 63;
    if (msg >= M_MSG) return;
    const float4* h4 = (const float4*)h;   // row stride 64
    const float4* U4 = (const float4*)U;   // row stride 64
    float4 r1 = *(const float4*)(EX + (size_t)mx[msg] * 768 + 512 + j * 4);
    float shx = 0, shy = 0, shz = 0, shw = 0;
    float sgx = 0, sgy = 0, sgz = 0, sgw = 0;
#pragma unroll
    for (int k = 0; k < 5; k++) {
        int gi = mg[msg * 5 + k];
        float4 hv = h4[(size_t)gi * 64 + j];
        float4 uh = U4[(size_t)gi * 64 + j];
        shx += hv.x; shy += hv.y; shz += hv.z; shw += hv.w;
        sgx += sgm(r1.x + uh.x) * hv.x;
        sgy += sgm(r1.y + uh.y) * hv.y;
        sgz += sgm(r1.z + uh.z) * hv.z;
        sgw += sgm(r1.w + uh.w) * hv.w;
    }
    size_t o = (size_t)msg * 256 + j * 4;
    *(uint2*)(shh + o) = make_uint2(pk2(shx, shy), pk2(shz, shw));
    *(uint2*)(shl + o) = make_uint2(pk2(lo_of(shx), lo_of(shy)), pk2(lo_of(shz), lo_of(shw)));
    *(uint2*)(sgh + o) = make_uint2(pk2(sgx, sgy), pk2(sgz, sgw));
    *(uint2*)(sgl + o) = make_uint2(pk2(lo_of(sgx), lo_of(sgy)), pk2(lo_of(sgz), lo_of(sgw)));
}

// Per-node neighbor-message sum -> bf16 split (GEMM A operand only).
__global__ void k_gnode(const int* __restrict__ ng, const float* __restrict__ h,
                        __nv_bfloat16* __restrict__ mnh, __nv_bfloat16* __restrict__ mnl) {
    int gt = blockIdx.x * blockDim.x + threadIdx.x;
    int n = gt >> 6;
    int j = gt & 63;
    if (n >= NNODE) return;
    const float4* h4 = (const float4*)h;
    float x = 0, y = 0, z = 0, w = 0;
#pragma unroll
    for (int k = 0; k < 5; k++) {
        int gi = ng[n * 5 + k];
        float4 hv = h4[(size_t)gi * 64 + j];
        x += hv.x; y += hv.y; z += hv.z; w += hv.w;
    }
    size_t o = (size_t)n * 256 + j * 4;
    *(uint2*)(mnh + o) = make_uint2(pk2(x, y), pk2(z, w));
    *(uint2*)(mnl + o) = make_uint2(pk2(lo_of(x), lo_of(y)), pk2(lo_of(z), lo_of(w)));
}

// Deterministic segment mean over sorted scope_ids.
__global__ void k_seg(const int* __restrict__ scope, const float* __restrict__ nv,
                      float* __restrict__ out) {
    int t = blockIdx.x;
    int j = threadIdx.x;
    int lo = 0, hi = NNODE;
    while (lo < hi) { int mid = (lo + hi) >> 1; if (scope[mid] < t) lo = mid + 1; else hi = mid; }
    int lo2 = lo, hi2 = NNODE;
    while (lo2 < hi2) { int mid = (lo2 + hi2) >> 1; if (scope[mid] < t + 1) lo2 = mid + 1; else hi2 = mid; }
    float s = 0.f;
    for (int r = lo; r < lo2; r++) s += nv[(size_t)r * HID + j];
    out[(size_t)t * HID + j] = s / fmaxf((float)(lo2 - lo), 1.f);
}

// ---------------- persistent tcgen05 split-bf16 GEMM, 128x256, K=256 -------
// All GEMMs: C[M,256] = A[M,256] @ B^T (B packed [n][k], bf16 hi/lo splits).
// MODE 0 (U):  C = Uh fp32
// MODE 1 (Z):  z = sigmoid(EXz[mx[m]] + C); t1 = (1-z)*sum_h;  write z, t1
// MODE 2 (H):  h = (t1 + z*tanh(EXh[mx[m]] + C)) * mask; write h fp32 + split
// MODE 3 (NV): nv = relu(EO[fnode[n]] + C)
struct TG {
    const __nv_bfloat16 *Ah, *Al;
    const __nv_bfloat16 *Bh, *Bl;
    float* C;
    float* C2;                              // t1 (Z)
    __nv_bfloat16 *Csh, *Csl;               // h split (H)
    const float* EXs;                        // EX+0 (Z) / EX+256 (H) / EO (NV)
    int exld;                                // 768 or 256
    const int* midx;                         // mx (Z,H) / fnode (NV)
    const float* zv; const float* t1v;       // (H)
    const __nv_bfloat16 *shh, *shl;          // (Z)
    int mt;                                  // number of 128-row tiles
};

#if TC_OK
template <int MODE>
__device__ __forceinline__ void epi(const TG& p, uint32_t dbase, int m0, int tid) {
    int w = tid >> 5, l = tid & 31;
    int row = (w & 3) * 32 + l;
    int m = m0 + row;
    int cb0 = (w >> 2) * 128;
    int mxm = (MODE != 0) ? __ldg(p.midx + m) : 0;
#pragma unroll 1
    for (int cb = 0; cb < 128; cb += 32) {
        uint32_t rr[32];
        tmem_ld32(rr, dbase + cb0 + cb);
        TC_WAIT_LD();
        int col = cb0 + cb;
        if (MODE == 0) {
            float* dst = p.C + (size_t)m * 256 + col;
#pragma unroll
            for (int j = 0; j < 8; j++)
                *(float4*)(dst + j * 4) = make_float4(
                    __uint_as_float(rr[j * 4 + 0]), __uint_as_float(rr[j * 4 + 1]),
                    __uint_as_float(rr[j * 4 + 2]), __uint_as_float(rr[j * 4 + 3]));
        } else if (MODE == 1) {
            const float* exz = p.EXs + (size_t)mxm * 768 + col;
            const __nv_bfloat16* hh = p.shh + (size_t)m * 256 + col;
            const __nv_bfloat16* hl = p.shl + (size_t)m * 256 + col;
            float* zd = p.C  + (size_t)m * 256 + col;
            float* td = p.C2 + (size_t)m * 256 + col;
#pragma unroll
            for (int j = 0; j < 8; j++) {
                float4 ex = *(const float4*)(exz + j * 4);
                float4 zz, tt;
                float sh0 = __bfloat162float(hh[j*4+0]) + __bfloat162float(hl[j*4+0]);
                float sh1 = __bfloat162float(hh[j*4+1]) + __bfloat162float(hl[j*4+1]);
                float sh2 = __bfloat162float(hh[j*4+2]) + __bfloat162float(hl[j*4+2]);
                float sh3 = __bfloat162float(hh[j*4+3]) + __bfloat162float(hl[j*4+3]);
                zz.x = sgm(ex.x + __uint_as_float(rr[j*4+0]));
                zz.y = sgm(ex.y + __uint_as_float(rr[j*4+1]));
                zz.z = sgm(ex.z + __uint_as_float(rr[j*4+2]));
                zz.w = sgm(ex.w + __uint_as_float(rr[j*4+3]));
                tt.x = (1.f - zz.x) * sh0; tt.y = (1.f - zz.y) * sh1;
                tt.z = (1.f - zz.z) * sh2; tt.w = (1.f - zz.w) * sh3;
                *(float4*)(zd + j * 4) = zz;
                *(float4*)(td + j * 4) = tt;
            }
        } else if (MODE == 2) {
            const float* exh = p.EXs + (size_t)mxm * 768 + col;
            const float* zvp = p.zv  + (size_t)m * 256 + col;
            const float* tvp = p.t1v + (size_t)m * 256 + col;
            float* hd = p.C + (size_t)m * 256 + col;
            __nv_bfloat16* sh = p.Csh + (size_t)m * 256 + col;
            __nv_bfloat16* sl = p.Csl + (size_t)m * 256 + col;
#pragma unroll
            for (int j = 0; j < 8; j++) {
                float4 ex = *(const float4*)(exh + j * 4);
                float4 zz = *(const float4*)(zvp + j * 4);
                float4 tt = *(const float4*)(tvp + j * 4);
                float4 hn;
                hn.x = tt.x + zz.x * tanhf(ex.x + __uint_as_float(rr[j*4+0]));
                hn.y = tt.y + zz.y * tanhf(ex.y + __uint_as_float(rr[j*4+1]));
                hn.z = tt.z + zz.z * tanhf(ex.z + __uint_as_float(rr[j*4+2]));
                hn.w = tt.w + zz.w * tanhf(ex.w + __uint_as_float(rr[j*4+3]));
                if (m == 0) hn = make_float4(0.f, 0.f, 0.f, 0.f);
                *(float4*)(hd + j * 4) = hn;
                size_t o = (size_t)m * 256 + col + j * 4;
                *(uint2*)(sh - ((size_t)m*256+col) + o) = make_uint2(pk2(hn.x, hn.y), pk2(hn.z, hn.w));
                *(uint2*)(sl - ((size_t)m*256+col) + o) =
                    make_uint2(pk2(lo_of(hn.x), lo_of(hn.y)), pk2(lo_of(hn.z), lo_of(hn.w)));
            }
        } else {
            const float* eo = p.EXs + (size_t)mxm * 256 + col;
            float* dst = p.C + (size_t)m * 256 + col;
#pragma unroll
            for (int j = 0; j < 8; j++) {
                float4 ex = *(const float4*)(eo + j * 4);
                *(float4*)(dst + j * 4) = make_float4(
                    fmaxf(ex.x + __uint_as_float(rr[j*4+0]), 0.f),
                    fmaxf(ex.y + __uint_as_float(rr[j*4+1]), 0.f),
                    fmaxf(ex.z + __uint_as_float(rr[j*4+2]), 0.f),
                    fmaxf(ex.w + __uint_as_float(rr[j*4+3]), 0.f));
            }
        }
    }
    TC_FENCE_BEFORE();
}
#endif

template <int MODE>
__global__ void __launch_bounds__(256) tgemm(TG p) {
    extern __shared__ char smraw[];
    char* sm = (char*)(((uintptr_t)smraw + 1023) & ~(uintptr_t)1023);
    uint32_t sb = su32(sm);
    (void)sb;
    const int tid = threadIdx.x;
#if TC_OK
    if (tid < 32) tc_alloc(sb + OFF_PTR, 512);
    if (tid == 0) {
        mbar_init(sb + OFF_MB + 0, 1);  mbar_init(sb + OFF_MB + 8, 1);
        mbar_init(sb + OFF_MB + 16, 1); mbar_init(sb + OFF_MB + 24, 1);
    }
    __syncthreads();
    uint32_t tmem = *(const uint32_t*)(sm + OFF_PTR);

    int ph0 = 0, ph1 = 0, tp0 = 0, tp1 = 0;
    int g = 0, lc = 0, prev_m0 = -1, prev_db = 0;

    for (int ti = blockIdx.x; ti < p.mt; ti += gridDim.x, lc++) {
        int m0 = ti * 128;
        int db = lc & 1;
        for (int c = 0; c < 4; c++) {
            int s = g & 1;
            if (g >= 2) {
                if (s == 0) { mbar_wait(sb + OFF_MB + 0, ph0); ph0 ^= 1; }
                else        { mbar_wait(sb + OFF_MB + 8, ph1); ph1 ^= 1; }
            }
            // stage A (prepacked bf16 hi/lo, pure copies, SW128)
            {
                int q = tid & 7, r0 = tid >> 3;
                const __nv_bfloat16* Ahg = p.Ah + (size_t)m0 * 256 + c * 64;
                const __nv_bfloat16* Alg = p.Al + (size_t)m0 * 256 + c * 64;
                char* dAh = sm + OFF_A(s, 0);
                char* dAl = sm + OFF_A(s, 1);
#pragma unroll
                for (int u = 0; u < 4; u++) {
                    int row = u * 32 + r0;
                    uint32_t sw = SWZ((uint32_t)(row * 128 + q * 16));
                    *(uint4*)(dAh + sw) = *(const uint4*)(Ahg + (size_t)row * 256 + q * 8);
                    *(uint4*)(dAl + sw) = *(const uint4*)(Alg + (size_t)row * 256 + q * 8);
                }
                const __nv_bfloat16* Bhg = p.Bh + c * 64;
                const __nv_bfloat16* Blg = p.Bl + c * 64;
                char* dBh = sm + OFF_B(s, 0);
                char* dBl = sm + OFF_B(s, 1);
#pragma unroll
                for (int v = 0; v < 8; v++) {
                    int row = v * 32 + r0;
                    uint32_t sw = SWZ((uint32_t)(row * 128 + q * 16));
                    *(uint4*)(dBh + sw) = *(const uint4*)(Bhg + (size_t)row * 256 + q * 8);
                    *(uint4*)(dBl + sw) = *(const uint4*)(Blg + (size_t)row * 256 + q * 8);
                }
            }
            FENCE_ASYNC();
            __syncthreads();
            if (tid < 32 && elect1()) {
                uint64_t ah = mk_desc(sb + OFF_A(s, 0));
                uint64_t al = mk_desc(sb + OFF_A(s, 1));
                uint64_t bh = mk_desc(sb + OFF_B(s, 0));
                uint64_t bl = mk_desc(sb + OFF_B(s, 1));
                uint32_t d = tmem + db * 256;
#pragma unroll
                for (int k = 0; k < 4; k++)
                    mma_f16_ss(d, ah + k * 2, bh + k * 2, IDESC, (c > 0) || (k > 0));
#pragma unroll
                for (int k = 0; k < 4; k++)
                    mma_f16_ss(d, ah + k * 2, bl + k * 2, IDESC, true);
#pragma unroll
                for (int k = 0; k < 4; k++)
                    mma_f16_ss(d, al + k * 2, bh + k * 2, IDESC, true);
                tc_commit(sb + OFF_MB + s * 8);
                if (c == 3) tc_commit(sb + OFF_MB + 16 + db * 8);
            }
            g++;
        }
        // deferred epilogue of previous tile (overlaps current tile's MMAs)
        if (prev_m0 >= 0) {
            if (prev_db == 0) { mbar_wait(sb + OFF_MB + 16, tp0); tp0 ^= 1; }
            else              { mbar_wait(sb + OFF_MB + 24, tp1); tp1 ^= 1; }
            TC_FENCE_AFTER();
            epi<MODE>(p, tmem + prev_db * 256, prev_m0, tid);
        }
        prev_m0 = m0; prev_db = db;
    }
    if (prev_m0 >= 0) {
        if (prev_db == 0) { mbar_wait(sb + OFF_MB + 16, tp0); tp0 ^= 1; }
        else              { mbar_wait(sb + OFF_MB + 24, tp1); tp1 ^= 1; }
        TC_FENCE_AFTER();
        epi<MODE>(p, tmem + prev_db * 256, prev_m0, tid);
    }
    __syncthreads();
    if (tid < 32) tc_dealloc(tmem, 512);
#else
    // Compile-only fallback for the plain compute_103 PTX pass (never run:
    // exact sm_103a SASS is embedded in the fatbin and always preferred).
    for (int ti = blockIdx.x; ti < p.mt; ti += gridDim.x) {
        int m0 = ti * 128;
        for (int e = tid; e < 128 * 256; e += 256) {
            int r = e >> 8, col = e & 255;
            int m = m0 + r;
            float acc = 0.f;
            for (int k = 0; k < 256; k++) {
                float a = __bfloat162float(p.Ah[(size_t)m * 256 + k])
                        + __bfloat162float(p.Al[(size_t)m * 256 + k]);
                float b = __bfloat162float(p.Bh[(size_t)col * 256 + k])
                        + __bfloat162float(p.Bl[(size_t)col * 256 + k]);
                acc += a * b;
            }
            if (MODE == 0) p.C[(size_t)m * 256 + col] = acc;
            else if (MODE == 1) {
                int mxm = p.midx[m];
                float z = sgm(p.EXs[(size_t)mxm * 768 + col] + acc);
                float sh = __bfloat162float(p.shh[(size_t)m * 256 + col])
                         + __bfloat162float(p.shl[(size_t)m * 256 + col]);
                p.C[(size_t)m * 256 + col] = z;
                p.C2[(size_t)m * 256 + col] = (1.f - z) * sh;
            } else if (MODE == 2) {
                int mxm = p.midx[m];
                float hn = p.t1v[(size_t)m * 256 + col]
                         + p.zv[(size_t)m * 256 + col]
                           * tanhf(p.EXs[(size_t)mxm * 768 + col] + acc);
                if (m == 0) hn = 0.f;
                p.C[(size_t)m * 256 + col] = hn;
                __nv_bfloat16 hb = __float2bfloat16(hn);
                p.Csh[(size_t)m * 256 + col] = hb;
                p.Csl[(size_t)m * 256 + col] = __float2bfloat16(hn - __bfloat162float(hb));
            } else {
                int fn = p.midx[m];
                p.C[(size_t)m * 256 + col] =
                    fmaxf(p.EXs[(size_t)fn * 256 + col] + acc, 0.f);
            }
        }
    }
#endif
}

// ---------------- orchestration --------------------------------------------
extern "C" void kernel_launch(void* const* d_in, const int* in_sizes, int n_in,
                              void* d_out, int out_size) {
    const int*   fnode = (const int*)d_in[0];
    const int*   fmess = (const int*)d_in[1];
    const int*   ng    = (const int*)d_in[2];
    const int*   mg    = (const int*)d_in[3];
    const int*   scope = (const int*)d_in[4];
    const float* emb   = (const float*)d_in[5];
    const float* Wz    = (const float*)d_in[6];
    const float* Wzb   = (const float*)d_in[7];
    const float* Wr    = (const float*)d_in[8];
    const float* Ur    = (const float*)d_in[9];
    const float* Urb   = (const float*)d_in[10];
    const float* Wh    = (const float*)d_in[11];
    const float* Whb   = (const float*)d_in[12];
    const float* Ow    = (const float*)d_in[13];
    const float* Ob    = (const float*)d_in[14];
    float* out = (float*)d_out;

    float *U, *h, *z, *t1, *nv, *EX, *EO; int* mx;
    __nv_bfloat16 *hh, *hl, *shh, *shl, *sgh, *sgl, *mnh, *mnl;
    __nv_bfloat16 *BUh, *BUl, *BZh, *BZl, *BHh, *BHl, *BOh, *BOl;
    cudaGetSymbolAddress((void**)&U,  g_U);
    cudaGetSymbolAddress((void**)&h,  g_h);
    cudaGetSymbolAddress((void**)&z,  g_zb);
    cudaGetSymbolAddress((void**)&t1, g_t1);
    cudaGetSymbolAddress((void**)&nv, g_nv);
    cudaGetSymbolAddress((void**)&EX, g_EX);
    cudaGetSymbolAddress((void**)&EO, g_EO);
    cudaGetSymbolAddress((void**)&mx, g_mx);
    cudaGetSymbolAddress((void**)&hh, g_hh);   cudaGetSymbolAddress((void**)&hl, g_hl);
    cudaGetSymbolAddress((void**)&shh, g_shh); cudaGetSymbolAddress((void**)&shl, g_shl);
    cudaGetSymbolAddress((void**)&sgh, g_sgh); cudaGetSymbolAddress((void**)&sgl, g_sgl);
    cudaGetSymbolAddress((void**)&mnh, g_mnh); cudaGetSymbolAddress((void**)&mnl, g_mnl);
    cudaGetSymbolAddress((void**)&BUh, g_BUh); cudaGetSymbolAddress((void**)&BUl, g_BUl);
    cudaGetSymbolAddress((void**)&BZh, g_BZh); cudaGetSymbolAddress((void**)&BZl, g_BZl);
    cudaGetSymbolAddress((void**)&BHh, g_BHh); cudaGetSymbolAddress((void**)&BHl, g_BHl);
    cudaGetSymbolAddress((void**)&BOh, g_BOh); cudaGetSymbolAddress((void**)&BOl, g_BOl);

    cudaFuncSetAttribute(tgemm<0>, cudaFuncAttributeMaxDynamicSharedMemorySize, TG_SMEM);
    cudaFuncSetAttribute(tgemm<1>, cudaFuncAttributeMaxDynamicSharedMemorySize, TG_SMEM);
    cudaFuncSetAttribute(tgemm<2>, cudaFuncAttributeMaxDynamicSharedMemorySize, TG_SMEM);
    cudaFuncSetAttribute(tgemm<3>, cudaFuncAttributeMaxDynamicSharedMemorySize, TG_SMEM);

    int nh = M_MSG * HID;
    k_zero2<<<(nh + 255) / 256, 256>>>(h, hh, hl, nh);
    k_pack<<<512, 256>>>(Wz, Wh, Ur, Ow, fnode, fmess, mx);
    k_prep<<<780, 256>>>(emb, Wz, Wh, Wr, Ow, Wzb, Whb, Urb, Ob, EX, EO);

    for (int d = 0; d < DEPTH; d++) {
        // Uh = h @ Ur
        TG pU{}; pU.Ah = hh; pU.Al = hl; pU.Bh = BUh; pU.Bl = BUl;
        pU.C = U; pU.mt = M_MSG / 128;
        tgemm<0><<<GRID_P, 256, TG_SMEM>>>(pU);
        // gather: sum_h, sum_gh (bf16 splits)
        k_gather<<<(M_MSG * 64) / 256, 256>>>(mg, h, U, EX, mx, shh, shl, sgh, sgl);
        // z = sigmoid(EXz[mx] + sum_h @ Wzh); t1 = (1-z)*sum_h
        TG pZ{}; pZ.Ah = shh; pZ.Al = shl; pZ.Bh = BZh; pZ.Bl = BZl;
        pZ.C = z; pZ.C2 = t1; pZ.EXs = EX; pZ.midx = mx;
        pZ.shh = shh; pZ.shl = shl; pZ.mt = M_MSG / 128;
        tgemm<1><<<GRID_P, 256, TG_SMEM>>>(pZ);
        // h = (t1 + z*tanh(EXh[mx] + sum_gh @ Whh)) * mask  -> fp32 + split
        TG pH{}; pH.Ah = sgh; pH.Al = sgl; pH.Bh = BHh; pH.Bl = BHl;
        pH.C = h; pH.Csh = hh; pH.Csl = hl; pH.EXs = EX + 256; pH.midx = mx;
        pH.zv = z; pH.t1v = t1; pH.mt = M_MSG / 128;
        tgemm<2><<<GRID_P, 256, TG_SMEM>>>(pH);
    }

    // mess_nei per node (bf16 split)
    k_gnode<<<(NNODE * 64) / 256, 256>>>(ng, h, mnh, mnl);

    // node_vec = relu(EO[fnode] + mn @ Ow2)
    TG pN{}; pN.Ah = mnh; pN.Al = mnl; pN.Bh = BOh; pN.Bl = BOl;
    pN.C = nv; pN.EXs = EO; pN.midx = fnode; pN.mt = NNODE / 128;
    tgemm<3><<<GRID_P, 256, TG_SMEM>>>(pN);

    // segment mean (sorted scopes, deterministic)
    k_seg<<<NTREE, 256>>>(scope, nv, out);
}

// round 9
// speedup vs baseline: 1.2650x; 1.2650x over previous
#include <cuda_runtime.h>
#include <cuda_bf16.h>
#include <cstdint>
#include <cstddef>

#define M_MSG 131072
#define NNODE 65536
#define HID   256
#define DEPTH 6
#define NTREE 2048
#define GRID_P 148

#if defined(__CUDA_ARCH_FEAT_SM103_ALL) || defined(__CUDA_ARCH_FEAT_SM100_ALL) || \
    defined(__CUDA_ARCH_FEAT_SM101_ALL) || defined(__CUDA_ARCH_FEAT_SM110_ALL)
#define TC_OK 1
#else
#define TC_OK 0
#endif

// ---------------- static device scratch ------------------------------------
// packed value = (bf16_hi_bits << 16) | bf16_lo_bits ; val = hi + lo
__device__ uint32_t g_hpk[(size_t)M_MSG * 256];     // h packed
__device__ uint32_t g_shp[(size_t)M_MSG * 256];     // sum_h packed
__device__ uint32_t g_sgp[(size_t)M_MSG * 256];     // sum_gh packed
__device__ unsigned short g_zu[(size_t)M_MSG * 256];// z gate u16 fixed point
__device__ __nv_bfloat16 g_Ub[(size_t)M_MSG * 512]; // U = h@[Ur|Wzh], bf16
__device__ uint32_t g_mnp[(size_t)NNODE * 256];     // mess_nei packed
__device__ float g_nv[(size_t)NNODE * 256];         // node_vec
__device__ float g_EX[780 * 768];                   // emb@[Wzx|Whx|Wr]+biases
__device__ float g_EO[780 * 256];                   // emb@Ow1+Ob
__device__ int   g_mx[M_MSG];                       // fnode[fmess[m]]
// bf16 hi/lo split weights, [n][k] layout (B operand = W^T)
__device__ __nv_bfloat16 g_BUh[512 * 256], g_BUl[512 * 256];  // [Ur|Wzh]^T
__device__ __nv_bfloat16 g_BHh[256 * 256], g_BHl[256 * 256];  // Whh^T
__device__ __nv_bfloat16 g_BOh[256 * 256], g_BOl[256 * 256];  // Ow2^T

// ---------------- packed bf16-pair helpers ----------------------------------
__device__ __forceinline__ float pk_dec(uint32_t p) {
    return __uint_as_float(p & 0xFFFF0000u) + __uint_as_float(p << 16);
}
__device__ __forceinline__ uint32_t pk_enc(float v) {
    __nv_bfloat16 hb = __float2bfloat16(v);
    float lo = v - __bfloat162float(hb);
    return ((uint32_t)__bfloat16_as_ushort(hb) << 16)
         | (uint32_t)__bfloat16_as_ushort(__float2bfloat16(lo));
}
__device__ __forceinline__ float bf_lo16(uint32_t u) { return __uint_as_float(u << 16); }
__device__ __forceinline__ float bf_hi16(uint32_t u) { return __uint_as_float(u & 0xFFFF0000u); }
__device__ __forceinline__ uint32_t bf2pk(float a, float b) {
    return (uint32_t)__bfloat16_as_ushort(__float2bfloat16(a))
         | ((uint32_t)__bfloat16_as_ushort(__float2bfloat16(b)) << 16);
}
__device__ __forceinline__ float sgm(float x) { return 1.0f / (1.0f + __expf(-x)); }

// ---------------- PTX helpers ------------------------------------------------
__device__ __forceinline__ uint32_t su32(const void* p) {
    uint32_t a;
    asm("{ .reg .u64 t; cvta.to.shared.u64 t, %1; cvt.u32.u64 %0, t; }"
        : "=r"(a) : "l"(p));
    return a;
}
#if TC_OK
__device__ __forceinline__ bool elect1() {
    uint32_t p;
    asm volatile("{\n\t.reg .pred p;\n\telect.sync _|p, 0xFFFFFFFF;\n\t"
                 "selp.b32 %0, 1, 0, p;\n\t}" : "=r"(p));
    return p != 0;
}
__device__ __forceinline__ void mbar_init(uint32_t a, uint32_t cnt) {
    asm volatile("mbarrier.init.shared.b64 [%0], %1;" :: "r"(a), "r"(cnt) : "memory");
}
__device__ __forceinline__ void mbar_wait(uint32_t a, int par) {
    asm volatile(
        "{\n\t.reg .pred P;\n"
        "W%=:\n\t"
        "mbarrier.try_wait.parity.acquire.cta.shared::cta.b64 P, [%0], %1, 0x989680;\n\t"
        "@P bra.uni D%=;\n\t"
        "bra.uni W%=;\n"
        "D%=:\n\t}" :: "r"(a), "r"(par) : "memory");
}
__device__ __forceinline__ void tc_alloc(uint32_t smem_res, uint32_t ncols) {
    asm volatile("tcgen05.alloc.cta_group::1.sync.aligned.shared::cta.b32 [%0], %1;"
                 :: "r"(smem_res), "r"(ncols) : "memory");
}
__device__ __forceinline__ void tc_dealloc(uint32_t tmem, uint32_t ncols) {
    asm volatile("tcgen05.dealloc.cta_group::1.sync.aligned.b32 %0, %1;"
                 :: "r"(tmem), "r"(ncols));
}
__device__ __forceinline__ void tc_commit(uint32_t mbar) {
    asm volatile("tcgen05.commit.cta_group::1.mbarrier::arrive::one.shared::cluster.b64 [%0];"
                 :: "r"(mbar) : "memory");
}
__device__ __forceinline__ void mma_f16_ss(uint32_t d, uint64_t ad, uint64_t bd,
                                           uint32_t idesc, bool acc) {
    uint32_t en = acc ? 1u : 0u;
    asm volatile(
        "{\n\t.reg .pred p;\n\tsetp.ne.u32 p, %5, 0;\n\t"
        "tcgen05.mma.cta_group::1.kind::f16 [%0], %1, %2, %3, {%4, %4, %4, %4}, p;\n\t}"
        :: "r"(d), "l"(ad), "l"(bd), "r"(idesc), "r"(0u), "r"(en) : "memory");
}
__device__ __forceinline__ void tmem_ld32(uint32_t* r, uint32_t addr) {
    asm volatile(
        "tcgen05.ld.sync.aligned.32x32b.x32.b32 "
        "{%0,%1,%2,%3,%4,%5,%6,%7,%8,%9,%10,%11,%12,%13,%14,%15,"
        "%16,%17,%18,%19,%20,%21,%22,%23,%24,%25,%26,%27,%28,%29,%30,%31}, [%32];"
        : "=r"(r[0]), "=r"(r[1]), "=r"(r[2]), "=r"(r[3]),
          "=r"(r[4]), "=r"(r[5]), "=r"(r[6]), "=r"(r[7]),
          "=r"(r[8]), "=r"(r[9]), "=r"(r[10]), "=r"(r[11]),
          "=r"(r[12]), "=r"(r[13]), "=r"(r[14]), "=r"(r[15]),
          "=r"(r[16]), "=r"(r[17]), "=r"(r[18]), "=r"(r[19]),
          "=r"(r[20]), "=r"(r[21]), "=r"(r[22]), "=r"(r[23]),
          "=r"(r[24]), "=r"(r[25]), "=r"(r[26]), "=r"(r[27]),
          "=r"(r[28]), "=r"(r[29]), "=r"(r[30]), "=r"(r[31])
        : "r"(addr));
}
#define TC_WAIT_LD()      asm volatile("tcgen05.wait::ld.sync.aligned;" ::: "memory")
#define TC_FENCE_AFTER()  asm volatile("tcgen05.fence::after_thread_sync;" ::: "memory")
#define TC_FENCE_BEFORE() asm volatile("tcgen05.fence::before_thread_sync;" ::: "memory")
#define FENCE_ASYNC()     asm volatile("fence.proxy.async.shared::cta;" ::: "memory")
#endif  // TC_OK

#define SWZ(o) ((o) ^ (((o) >> 3) & 0x70))

__device__ __forceinline__ uint64_t mk_desc(uint32_t addr) {
    return (2ull << 61) | (1ull << 46) | (64ull << 32) | (1ull << 16)
         | ((uint64_t)(addr >> 4) & 0x3FFF);
}

// idesc: dtype=F32, a=BF16, b=BF16, N=128, M=128
static constexpr uint32_t IDESC =
    (1u << 4) | (1u << 7) | (1u << 10) | ((128u / 8) << 17) | ((128u / 16) << 24);

// SMEM layout (bytes from 1024-aligned base)
#define OFF_PTR   0
#define OFF_MB    16                  // chunk mbars @16,24; tile mbars @32,40
#define OFF_A(s, t) (1024 + (s) * 32768 + (t) * 16384)
#define OFF_BR    66560               // 4 chunks x (hi,lo) x 16KB = 128KB
#define TG_SMEM   199680

// ---------------- small kernels ---------------------------------------------
__global__ void k_zero(uint32_t* p, int n) {
    int i = blockIdx.x * blockDim.x + threadIdx.x;
    if (i < n) p[i] = 0u;
}

__device__ __forceinline__ void bsplit(float w, __nv_bfloat16* H, __nv_bfloat16* L, int i) {
    __nv_bfloat16 h = __float2bfloat16(w);
    H[i] = h;
    L[i] = __float2bfloat16(w - __bfloat162float(h));
}

__global__ void k_pack(const float* __restrict__ Wz, const float* __restrict__ Wh,
                       const float* __restrict__ Ur, const float* __restrict__ Ow,
                       const int* __restrict__ fnode, const int* __restrict__ fmess,
                       int* __restrict__ mx) {
    int i = blockIdx.x * blockDim.x + threadIdx.x;
    int st = gridDim.x * blockDim.x;
    for (int t = i; t < 512 * 256; t += st) {
        int n = t >> 8, k = t & 255;
        float w = (n < 256) ? Ur[k * 256 + n] : Wz[(256 + k) * 256 + (n - 256)];
        bsplit(w, g_BUh, g_BUl, t);
    }
    for (int t = i; t < 256 * 256; t += st) {
        int n = t >> 8, k = t & 255;
        bsplit(Wh[(256 + k) * 256 + n], g_BHh, g_BHl, t);
        bsplit(Ow[(256 + k) * 256 + n], g_BOh, g_BOl, t);
    }
    for (int t = i; t < M_MSG; t += st) mx[t] = fnode[fmess[t]];
}

// EX/EO tables: per-vocab precompute of all x-dependent matmuls.
__global__ void k_prep(const float* __restrict__ emb,
                       const float* __restrict__ Wz, const float* __restrict__ Wh,
                       const float* __restrict__ Wr, const float* __restrict__ Ow,
                       const float* __restrict__ Wzb, const float* __restrict__ Whb,
                       const float* __restrict__ Urb, const float* __restrict__ Ob,
                       float* __restrict__ EX, float* __restrict__ EO) {
    __shared__ float e[256];
    int v = blockIdx.x, j = threadIdx.x;
    e[j] = emb[v * 256 + j];
    __syncthreads();
    float s0 = 0, s1 = 0, s2 = 0, s3 = 0;
#pragma unroll 4
    for (int k = 0; k < 256; k++) {
        float ek = e[k];
        s0 = fmaf(ek, Wz[k * 256 + j], s0);
        s1 = fmaf(ek, Wh[k * 256 + j], s1);
        s2 = fmaf(ek, Wr[k * 256 + j], s2);
        s3 = fmaf(ek, Ow[k * 256 + j], s3);
    }
    EX[v * 768 + j]       = s0 + Wzb[j];
    EX[v * 768 + 256 + j] = s1 + Whb[j];
    EX[v * 768 + 512 + j] = s2 + Urb[j];
    EO[v * 256 + j]       = s3 + Ob[j];
}

// Fused gather: sum_h, z = sigmoid(xz + sum(hz)), sum_gh. 64 thr/msg.
__global__ void k_gather(const int* __restrict__ mg, const uint32_t* __restrict__ hpk,
                         const __nv_bfloat16* __restrict__ Ub,
                         const float* __restrict__ EX, const int* __restrict__ mx,
                         uint32_t* __restrict__ shp, uint32_t* __restrict__ sgp,
                         unsigned short* __restrict__ zu) {
    int gt = blockIdx.x * blockDim.x + threadIdx.x;
    int msg = gt >> 6;
    int j = gt & 63;
    if (msg >= M_MSG) return;
    int mxv = __ldg(mx + msg);
    float4 xz = *(const float4*)(EX + (size_t)mxv * 768 + j * 4);
    float4 r1 = *(const float4*)(EX + (size_t)mxv * 768 + 512 + j * 4);
    float sh0 = 0, sh1 = 0, sh2 = 0, sh3 = 0;
    float sz0 = xz.x, sz1 = xz.y, sz2 = xz.z, sz3 = xz.w;
    float sg0 = 0, sg1 = 0, sg2 = 0, sg3 = 0;
    const uint4* h4 = (const uint4*)hpk;
#pragma unroll
    for (int k = 0; k < 5; k++) {
        int gi = __ldg(mg + msg * 5 + k);
        uint4 hp = h4[(size_t)gi * 64 + j];
        float h0 = pk_dec(hp.x), h1 = pk_dec(hp.y), h2 = pk_dec(hp.z), h3 = pk_dec(hp.w);
        uint2 uu = *(const uint2*)(Ub + (size_t)gi * 512 + j * 4);
        uint2 uz = *(const uint2*)(Ub + (size_t)gi * 512 + 256 + j * 4);
        sh0 += h0; sh1 += h1; sh2 += h2; sh3 += h3;
        sz0 += bf_lo16(uz.x); sz1 += bf_hi16(uz.x);
        sz2 += bf_lo16(uz.y); sz3 += bf_hi16(uz.y);
        sg0 += sgm(r1.x + bf_lo16(uu.x)) * h0;
        sg1 += sgm(r1.y + bf_hi16(uu.x)) * h1;
        sg2 += sgm(r1.z + bf_lo16(uu.y)) * h2;
        sg3 += sgm(r1.w + bf_hi16(uu.y)) * h3;
    }
    float z0 = sgm(sz0), z1 = sgm(sz1), z2 = sgm(sz2), z3 = sgm(sz3);
    size_t o = (size_t)msg * 64 + j;
    ((uint4*)shp)[o] = make_uint4(pk_enc(sh0), pk_enc(sh1), pk_enc(sh2), pk_enc(sh3));
    ((uint4*)sgp)[o] = make_uint4(pk_enc(sg0), pk_enc(sg1), pk_enc(sg2), pk_enc(sg3));
    uint2 zw;
    zw.x = (uint32_t)__float2uint_rn(z0 * 65535.f) | ((uint32_t)__float2uint_rn(z1 * 65535.f) << 16);
    zw.y = (uint32_t)__float2uint_rn(z2 * 65535.f) | ((uint32_t)__float2uint_rn(z3 * 65535.f) << 16);
    ((uint2*)zu)[o] = zw;
}

// Per-node neighbor-message sum (packed in, packed out).
__global__ void k_gnode(const int* __restrict__ ng, const uint32_t* __restrict__ hpk,
                        uint32_t* __restrict__ mnp) {
    int gt = blockIdx.x * blockDim.x + threadIdx.x;
    int n = gt >> 6;
    int j = gt & 63;
    if (n >= NNODE) return;
    const uint4* h4 = (const uint4*)hpk;
    float x = 0, y = 0, z = 0, w = 0;
#pragma unroll
    for (int k = 0; k < 5; k++) {
        int gi = __ldg(ng + n * 5 + k);
        uint4 hp = h4[(size_t)gi * 64 + j];
        x += pk_dec(hp.x); y += pk_dec(hp.y); z += pk_dec(hp.z); w += pk_dec(hp.w);
    }
    ((uint4*)mnp)[(size_t)n * 64 + j] = make_uint4(pk_enc(x), pk_enc(y), pk_enc(z), pk_enc(w));
}

// Deterministic segment mean over sorted scope_ids.
__global__ void k_seg(const int* __restrict__ scope, const float* __restrict__ nv,
                      float* __restrict__ out) {
    int t = blockIdx.x;
    int j = threadIdx.x;
    int lo = 0, hi = NNODE;
    while (lo < hi) { int mid = (lo + hi) >> 1; if (scope[mid] < t) lo = mid + 1; else hi = mid; }
    int lo2 = lo, hi2 = NNODE;
    while (lo2 < hi2) { int mid = (lo2 + hi2) >> 1; if (scope[mid] < t + 1) lo2 = mid + 1; else hi2 = mid; }
    float s = 0.f;
    for (int r = lo; r < lo2; r++) s += nv[(size_t)r * HID + j];
    out[(size_t)t * HID + j] = s / fmaxf((float)(lo2 - lo), 1.f);
}

// ---------------- persistent tcgen05 GEMM, 128x128 tile, B SMEM-resident ----
// C[m, n0:n0+128] = dec(Apk[m,:256]) @ B^T slice. 3 MMAs (hh,hl,lh) per K16.
// MODE 0 (U):  write bf16 C into Ub[m*512 + n0 + col]
// MODE 2 (H):  h = (1-z)*sum_h + z*tanh(EXh[mx[m]] + C); mask row0; write packed
// MODE 3 (NV): nv = relu(EO[fnode[m]] + C)
struct TG {
    const uint32_t* Apk;
    const __nv_bfloat16 *Bh, *Bl;
    __nv_bfloat16* Ubf;
    const float* EX; const int* mx;
    const unsigned short* zu; const uint32_t* shp;
    uint32_t* hpk;
    const float* EO; const int* fn; float* nv;
    int mT, nT;
};

#if TC_OK
template <int MODE>
__device__ __forceinline__ void epi(const TG& p, uint32_t dbase, int m0, int n0, int tid) {
    int w = tid >> 5, l = tid & 31;
    int row = (w & 3) * 32 + l;
    int m = m0 + row;
    int ch = w >> 2;                      // column half (64 cols each)
    int mxm = 0;
    if (MODE == 2) mxm = __ldg(p.mx + m);
    if (MODE == 3) mxm = __ldg(p.fn + m);
#pragma unroll 1
    for (int cb2 = 0; cb2 < 2; cb2++) {
        int colloc = ch * 64 + cb2 * 32;
        uint32_t rr[32];
        tmem_ld32(rr, dbase + colloc);
        TC_WAIT_LD();
        int col = n0 + colloc;
        if (MODE == 0) {
            uint4* dst = (uint4*)(p.Ubf + (size_t)m * 512 + col);
#pragma unroll
            for (int i2 = 0; i2 < 4; i2++)
                dst[i2] = make_uint4(
                    bf2pk(__uint_as_float(rr[i2*8+0]), __uint_as_float(rr[i2*8+1])),
                    bf2pk(__uint_as_float(rr[i2*8+2]), __uint_as_float(rr[i2*8+3])),
                    bf2pk(__uint_as_float(rr[i2*8+4]), __uint_as_float(rr[i2*8+5])),
                    bf2pk(__uint_as_float(rr[i2*8+6]), __uint_as_float(rr[i2*8+7])));
        } else if (MODE == 2) {
            const float4* xh4 = (const float4*)(p.EX + (size_t)mxm * 768 + 256 + col);
            const uint4* sp4 = (const uint4*)(p.shp + (size_t)m * 256 + col);
            const uint2* zp2 = (const uint2*)(p.zu + (size_t)m * 256 + col);
            uint4* hd = (uint4*)(p.hpk + (size_t)m * 256 + col);
            const float inv = 1.f / 65535.f;
#pragma unroll
            for (int j2 = 0; j2 < 8; j2++) {
                float4 xh = xh4[j2];
                uint4 sp = sp4[j2];
                uint2 zz = zp2[j2];
                float z0 = (float)(zz.x & 0xFFFF) * inv, z1 = (float)(zz.x >> 16) * inv;
                float z2 = (float)(zz.y & 0xFFFF) * inv, z3 = (float)(zz.y >> 16) * inv;
                float h0 = (1.f - z0) * pk_dec(sp.x) + z0 * tanhf(xh.x + __uint_as_float(rr[j2*4+0]));
                float h1 = (1.f - z1) * pk_dec(sp.y) + z1 * tanhf(xh.y + __uint_as_float(rr[j2*4+1]));
                float h2 = (1.f - z2) * pk_dec(sp.z) + z2 * tanhf(xh.z + __uint_as_float(rr[j2*4+2]));
                float h3 = (1.f - z3) * pk_dec(sp.w) + z3 * tanhf(xh.w + __uint_as_float(rr[j2*4+3]));
                if (m == 0) { h0 = h1 = h2 = h3 = 0.f; }
                hd[j2] = make_uint4(pk_enc(h0), pk_enc(h1), pk_enc(h2), pk_enc(h3));
            }
        } else {
            const float4* eo4 = (const float4*)(p.EO + (size_t)mxm * 256 + col);
            float4* dst = (float4*)(p.nv + (size_t)m * 256 + col);
#pragma unroll
            for (int j2 = 0; j2 < 8; j2++) {
                float4 eo = eo4[j2];
                dst[j2] = make_float4(
                    fmaxf(eo.x + __uint_as_float(rr[j2*4+0]), 0.f),
                    fmaxf(eo.y + __uint_as_float(rr[j2*4+1]), 0.f),
                    fmaxf(eo.z + __uint_as_float(rr[j2*4+2]), 0.f),
                    fmaxf(eo.w + __uint_as_float(rr[j2*4+3]), 0.f));
            }
        }
    }
    TC_FENCE_BEFORE();
}
#endif

template <int MODE>
__global__ void __launch_bounds__(256) tgemm(TG p) {
    extern __shared__ char smraw[];
    char* sm = (char*)(((uintptr_t)smraw + 1023) & ~(uintptr_t)1023);
    const int tid = threadIdx.x;
#if TC_OK
    uint32_t sb = su32(sm);
    if (tid < 32) tc_alloc(sb + OFF_PTR, 256);
    if (tid == 0) {
        mbar_init(sb + OFF_MB + 0, 1);  mbar_init(sb + OFF_MB + 8, 1);
        mbar_init(sb + OFF_MB + 16, 1); mbar_init(sb + OFF_MB + 24, 1);
    }
    __syncthreads();
    uint32_t tmem = *(const uint32_t*)(sm + OFF_PTR);

    int ph0 = 0, ph1 = 0, pend0 = 0, pend1 = 0;
    int tp0 = 0, tp1 = 0;
    int prev_m0 = -1, prev_db = 0, prev_n0 = 0;
    int curn = -1, lc = 0;
    const int TT = p.mT * p.nT;

    for (int ti = blockIdx.x; ti < TT; ti += gridDim.x, lc++) {
        int nt = ti / p.mT, mt = ti - nt * p.mT;
        int m0 = mt * 128, n0 = nt * 128;
        if (nt != curn) {
            // drain: all MMAs must finish before B restage
            if (pend0) { mbar_wait(sb + OFF_MB + 0, ph0); ph0 ^= 1; pend0 = 0; }
            if (pend1) { mbar_wait(sb + OFF_MB + 8, ph1); ph1 ^= 1; pend1 = 0; }
            if (prev_m0 >= 0) {
                if (prev_db == 0) { mbar_wait(sb + OFF_MB + 16, tp0); tp0 ^= 1; }
                else              { mbar_wait(sb + OFF_MB + 24, tp1); tp1 ^= 1; }
                TC_FENCE_AFTER();
                epi<MODE>(p, tmem + prev_db * 128, prev_m0, prev_n0, tid);
                prev_m0 = -1;
            }
            __syncthreads();
            // stage resident B slice: 4 K-chunk tiles x (hi,lo), SW128
            {
                int q = tid & 7, r0 = tid >> 3;
#pragma unroll
                for (int cc = 0; cc < 4; cc++) {
#pragma unroll
                    for (int u = 0; u < 4; u++) {
                        int row = u * 32 + r0;
                        size_t go = (size_t)(n0 + row) * 256 + cc * 64 + q * 8;
                        uint32_t sw = SWZ((uint32_t)(row * 128 + q * 16));
                        *(uint4*)(sm + OFF_BR + cc * 32768 + sw) =
                            *(const uint4*)(p.Bh + go);
                        *(uint4*)(sm + OFF_BR + cc * 32768 + 16384 + sw) =
                            *(const uint4*)(p.Bl + go);
                    }
                }
            }
            curn = nt;
        }
        int db = lc & 1;
        for (int c = 0; c < 4; c++) {
            int s = c & 1;
            if (s == 0) { if (pend0) { mbar_wait(sb + OFF_MB + 0, ph0); ph0 ^= 1; pend0 = 0; } }
            else        { if (pend1) { mbar_wait(sb + OFF_MB + 8, ph1); ph1 ^= 1; pend1 = 0; } }
            // stage A chunk: packed -> hi/lo bf16 tiles (PRMT decode), SW128
            {
                int q = tid & 15, r0 = tid >> 4;
                const uint4* Ag = (const uint4*)(p.Apk + (size_t)m0 * 256) + c * 16;
                char* dAh = sm + OFF_A(s, 0);
                char* dAl = sm + OFF_A(s, 1);
#pragma unroll
                for (int u = 0; u < 8; u++) {
                    int row = u * 16 + r0;
                    uint4 pk = Ag[(size_t)row * 64 + q];
                    uint32_t sw = SWZ((uint32_t)(row * 128 + q * 8));
                    *(uint2*)(dAh + sw) = make_uint2(__byte_perm(pk.x, pk.y, 0x7632),
                                                     __byte_perm(pk.z, pk.w, 0x7632));
                    *(uint2*)(dAl + sw) = make_uint2(__byte_perm(pk.x, pk.y, 0x5410),
                                                     __byte_perm(pk.z, pk.w, 0x5410));
                }
            }
            FENCE_ASYNC();
            __syncthreads();
            if (tid < 32 && elect1()) {
                uint64_t ah = mk_desc(sb + OFF_A(s, 0));
                uint64_t al = mk_desc(sb + OFF_A(s, 1));
                uint64_t bh = mk_desc(sb + OFF_BR + c * 32768);
                uint64_t bl = mk_desc(sb + OFF_BR + c * 32768 + 16384);
                uint32_t d = tmem + db * 128;
#pragma unroll
                for (int k = 0; k < 4; k++)
                    mma_f16_ss(d, ah + k * 2, bh + k * 2, IDESC, (c > 0) || (k > 0));
#pragma unroll
                for (int k = 0; k < 4; k++)
                    mma_f16_ss(d, ah + k * 2, bl + k * 2, IDESC, true);
#pragma unroll
                for (int k = 0; k < 4; k++)
                    mma_f16_ss(d, al + k * 2, bh + k * 2, IDESC, true);
                tc_commit(sb + OFF_MB + s * 8);
                if (c == 3) tc_commit(sb + OFF_MB + 16 + db * 8);
            }
            if (s == 0) pend0 = 1; else pend1 = 1;
        }
        // deferred epilogue of previous tile (overlaps this tile's MMAs)
        if (prev_m0 >= 0) {
            if (prev_db == 0) { mbar_wait(sb + OFF_MB + 16, tp0); tp0 ^= 1; }
            else              { mbar_wait(sb + OFF_MB + 24, tp1); tp1 ^= 1; }
            TC_FENCE_AFTER();
            epi<MODE>(p, tmem + prev_db * 128, prev_m0, prev_n0, tid);
        }
        prev_m0 = m0; prev_db = db; prev_n0 = n0;
    }
    if (prev_m0 >= 0) {
        if (prev_db == 0) { mbar_wait(sb + OFF_MB + 16, tp0); tp0 ^= 1; }
        else              { mbar_wait(sb + OFF_MB + 24, tp1); tp1 ^= 1; }
        TC_FENCE_AFTER();
        epi<MODE>(p, tmem + prev_db * 128, prev_m0, prev_n0, tid);
    }
    __syncthreads();
    if (tid < 32) tc_dealloc(tmem, 256);
#else
    // Compile-only fallback for the plain compute_103 PTX pass (never run:
    // exact sm_103a SASS is embedded in the fatbin and always preferred).
    int Mtot = p.mT * 128, Ntot = p.nT * 128;
    for (int m = blockIdx.x; m < Mtot; m += gridDim.x) {
        for (int col = tid; col < Ntot; col += blockDim.x) {
            float acc = 0.f;
            for (int k = 0; k < 256; k++) {
                float a = pk_dec(p.Apk[(size_t)m * 256 + k]);
                float b = __bfloat162float(p.Bh[(size_t)col * 256 + k])
                        + __bfloat162float(p.Bl[(size_t)col * 256 + k]);
                acc += a * b;
            }
            if (MODE == 0) {
                p.Ubf[(size_t)m * 512 + col] = __float2bfloat16(acc);
            } else if (MODE == 2) {
                int mxm = p.mx[m];
                float z = (float)p.zu[(size_t)m * 256 + col] * (1.f / 65535.f);
                float sh = pk_dec(p.shp[(size_t)m * 256 + col]);
                float h = (1.f - z) * sh
                        + z * tanhf(p.EX[(size_t)mxm * 768 + 256 + col] + acc);
                if (m == 0) h = 0.f;
                p.hpk[(size_t)m * 256 + col] = pk_enc(h);
            } else {
                int fn = p.fn[m];
                p.nv[(size_t)m * 256 + col] =
                    fmaxf(p.EO[(size_t)fn * 256 + col] + acc, 0.f);
            }
        }
    }
#endif
}

// ---------------- orchestration --------------------------------------------
extern "C" void kernel_launch(void* const* d_in, const int* in_sizes, int n_in,
                              void* d_out, int out_size) {
    const int*   fnode = (const int*)d_in[0];
    const int*   fmess = (const int*)d_in[1];
    const int*   ng    = (const int*)d_in[2];
    const int*   mg    = (const int*)d_in[3];
    const int*   scope = (const int*)d_in[4];
    const float* emb   = (const float*)d_in[5];
    const float* Wz    = (const float*)d_in[6];
    const float* Wzb   = (const float*)d_in[7];
    const float* Wr    = (const float*)d_in[8];
    const float* Ur    = (const float*)d_in[9];
    const float* Urb   = (const float*)d_in[10];
    const float* Wh    = (const float*)d_in[11];
    const float* Whb   = (const float*)d_in[12];
    const float* Ow    = (const float*)d_in[13];
    const float* Ob    = (const float*)d_in[14];
    float* out = (float*)d_out;

    uint32_t *hpk, *shp, *sgp, *mnp;
    unsigned short* zu;
    __nv_bfloat16 *Ub, *BUh, *BUl, *BHh, *BHl, *BOh, *BOl;
    float *nv, *EX, *EO;
    int* mx;
    cudaGetSymbolAddress((void**)&hpk, g_hpk);
    cudaGetSymbolAddress((void**)&shp, g_shp);
    cudaGetSymbolAddress((void**)&sgp, g_sgp);
    cudaGetSymbolAddress((void**)&zu,  g_zu);
    cudaGetSymbolAddress((void**)&Ub,  g_Ub);
    cudaGetSymbolAddress((void**)&mnp, g_mnp);
    cudaGetSymbolAddress((void**)&nv,  g_nv);
    cudaGetSymbolAddress((void**)&EX,  g_EX);
    cudaGetSymbolAddress((void**)&EO,  g_EO);
    cudaGetSymbolAddress((void**)&mx,  g_mx);
    cudaGetSymbolAddress((void**)&BUh, g_BUh); cudaGetSymbolAddress((void**)&BUl, g_BUl);
    cudaGetSymbolAddress((void**)&BHh, g_BHh); cudaGetSymbolAddress((void**)&BHl, g_BHl);
    cudaGetSymbolAddress((void**)&BOh, g_BOh); cudaGetSymbolAddress((void**)&BOl, g_BOl);

    cudaFuncSetAttribute(tgemm<0>, cudaFuncAttributeMaxDynamicSharedMemorySize, TG_SMEM);
    cudaFuncSetAttribute(tgemm<2>, cudaFuncAttributeMaxDynamicSharedMemorySize, TG_SMEM);
    cudaFuncSetAttribute(tgemm<3>, cudaFuncAttributeMaxDynamicSharedMemorySize, TG_SMEM);

    k_zero<<<(M_MSG * 256) / 256, 256>>>(hpk, M_MSG * 256);
    k_pack<<<512, 256>>>(Wz, Wh, Ur, Ow, fnode, fmess, mx);
    k_prep<<<780, 256>>>(emb, Wz, Wh, Wr, Ow, Wzb, Whb, Urb, Ob, EX, EO);

    for (int d = 0; d < DEPTH; d++) {
        // U = h @ [Ur | Wzh]  (bf16 out)
        TG pU{}; pU.Apk = hpk; pU.Bh = BUh; pU.Bl = BUl; pU.Ubf = Ub;
        pU.mT = M_MSG / 128; pU.nT = 4;
        tgemm<0><<<GRID_P, 256, TG_SMEM>>>(pU);
        // gather: sum_h, z, sum_gh
        k_gather<<<(M_MSG * 64) / 256, 256>>>(mg, hpk, Ub, EX, mx, shp, sgp, zu);
        // h = (1-z)*sum_h + z*tanh(EXh[mx] + sum_gh @ Whh), mask row0
        TG pH{}; pH.Apk = sgp; pH.Bh = BHh; pH.Bl = BHl;
        pH.EX = EX; pH.mx = mx; pH.zu = zu; pH.shp = shp; pH.hpk = hpk;
        pH.mT = M_MSG / 128; pH.nT = 2;
        tgemm<2><<<GRID_P, 256, TG_SMEM>>>(pH);
    }

    // mess_nei per node (packed)
    k_gnode<<<(NNODE * 64) / 256, 256>>>(ng, hpk, mnp);

    // node_vec = relu(EO[fnode] + mn @ Ow2)
    TG pN{}; pN.Apk = mnp; pN.Bh = BOh; pN.Bl = BOl;
    pN.EO = EO; pN.fn = fnode; pN.nv = nv;
    pN.mT = NNODE / 128; pN.nT = 2;
    tgemm<3><<<GRID_P, 256, TG_SMEM>>>(pN);

    // segment mean (sorted scopes, deterministic)
    k_seg<<<NTREE, 256>>>(scope, nv, out);
}

// round 10
// speedup vs baseline: 1.3184x; 1.0422x over previous
#include <cuda_runtime.h>
#include <cuda_bf16.h>
#include <cstdint>
#include <cstddef>

#define M_MSG 131072
#define NNODE 65536
#define HID   256
#define DEPTH 6
#define NTREE 2048
#define GRID_P 148

#if defined(__CUDA_ARCH_FEAT_SM103_ALL) || defined(__CUDA_ARCH_FEAT_SM100_ALL) || \
    defined(__CUDA_ARCH_FEAT_SM101_ALL) || defined(__CUDA_ARCH_FEAT_SM110_ALL)
#define TC_OK 1
#else
#define TC_OK 0
#endif

// ---------------- static device scratch ------------------------------------
// packed value = (bf16_hi_bits << 16) | bf16_lo_bits ; val = hi + lo
__device__ uint32_t g_hpk[(size_t)M_MSG * 256];     // h packed
__device__ uint32_t g_shp[(size_t)M_MSG * 256];     // sum_h packed
__device__ uint32_t g_sgp[(size_t)M_MSG * 256];     // sum_gh packed
__device__ unsigned short g_zu[(size_t)M_MSG * 256];// z gate u16 fixed point
__device__ __nv_bfloat16 g_Ub[(size_t)M_MSG * 256]; // Uh = h@Ur, bf16
__device__ uint32_t g_mnp[(size_t)NNODE * 256];     // mess_nei packed
__device__ float g_nv[(size_t)NNODE * 256];         // node_vec
__device__ float g_EX[780 * 768];                   // emb@[Wzx|Whx|Wr]+biases
__device__ float g_EO[780 * 256];                   // emb@Ow1+Ob
__device__ int   g_mx[M_MSG];                       // fnode[fmess[m]]
// bf16 hi/lo split weights, [n][k] layout (B operand = W^T), all 256x256
__device__ __nv_bfloat16 g_BUh[256 * 256], g_BUl[256 * 256];  // Ur^T
__device__ __nv_bfloat16 g_BZh[256 * 256], g_BZl[256 * 256];  // Wzh^T
__device__ __nv_bfloat16 g_BHh[256 * 256], g_BHl[256 * 256];  // Whh^T
__device__ __nv_bfloat16 g_BOh[256 * 256], g_BOl[256 * 256];  // Ow2^T

// ---------------- packed bf16-pair helpers ----------------------------------
__device__ __forceinline__ float pk_dec(uint32_t p) {
    return __uint_as_float(p & 0xFFFF0000u) + __uint_as_float(p << 16);
}
__device__ __forceinline__ uint32_t pk_enc(float v) {
    __nv_bfloat16 hb = __float2bfloat16(v);
    float lo = v - __bfloat162float(hb);
    return ((uint32_t)__bfloat16_as_ushort(hb) << 16)
         | (uint32_t)__bfloat16_as_ushort(__float2bfloat16(lo));
}
__device__ __forceinline__ float bf_lo16(uint32_t u) { return __uint_as_float(u << 16); }
__device__ __forceinline__ float bf_hi16(uint32_t u) { return __uint_as_float(u & 0xFFFF0000u); }
__device__ __forceinline__ uint32_t bf2pk(float a, float b) {
    return (uint32_t)__bfloat16_as_ushort(__float2bfloat16(a))
         | ((uint32_t)__bfloat16_as_ushort(__float2bfloat16(b)) << 16);
}
__device__ __forceinline__ float sgm(float x) { return 1.0f / (1.0f + __expf(-x)); }

// ---------------- PTX helpers ------------------------------------------------
__device__ __forceinline__ uint32_t su32(const void* p) {
    uint32_t a;
    asm("{ .reg .u64 t; cvta.to.shared.u64 t, %1; cvt.u32.u64 %0, t; }"
        : "=r"(a) : "l"(p));
    return a;
}
#if TC_OK
__device__ __forceinline__ bool elect1() {
    uint32_t p;
    asm volatile("{\n\t.reg .pred p;\n\telect.sync _|p, 0xFFFFFFFF;\n\t"
                 "selp.b32 %0, 1, 0, p;\n\t}" : "=r"(p));
    return p != 0;
}
__device__ __forceinline__ void mbar_init(uint32_t a, uint32_t cnt) {
    asm volatile("mbarrier.init.shared.b64 [%0], %1;" :: "r"(a), "r"(cnt) : "memory");
}
__device__ __forceinline__ void mbar_wait(uint32_t a, int par) {
    asm volatile(
        "{\n\t.reg .pred P;\n"
        "W%=:\n\t"
        "mbarrier.try_wait.parity.acquire.cta.shared::cta.b64 P, [%0], %1, 0x989680;\n\t"
        "@P bra.uni D%=;\n\t"
        "bra.uni W%=;\n"
        "D%=:\n\t}" :: "r"(a), "r"(par) : "memory");
}
__device__ __forceinline__ void tc_alloc(uint32_t smem_res, uint32_t ncols) {
    asm volatile("tcgen05.alloc.cta_group::1.sync.aligned.shared::cta.b32 [%0], %1;"
                 :: "r"(smem_res), "r"(ncols) : "memory");
}
__device__ __forceinline__ void tc_dealloc(uint32_t tmem, uint32_t ncols) {
    asm volatile("tcgen05.dealloc.cta_group::1.sync.aligned.b32 %0, %1;"
                 :: "r"(tmem), "r"(ncols));
}
__device__ __forceinline__ void tc_commit(uint32_t mbar) {
    asm volatile("tcgen05.commit.cta_group::1.mbarrier::arrive::one.shared::cluster.b64 [%0];"
                 :: "r"(mbar) : "memory");
}
__device__ __forceinline__ void mma_f16_ss(uint32_t d, uint64_t ad, uint64_t bd,
                                           uint32_t idesc, bool acc) {
    uint32_t en = acc ? 1u : 0u;
    asm volatile(
        "{\n\t.reg .pred p;\n\tsetp.ne.u32 p, %5, 0;\n\t"
        "tcgen05.mma.cta_group::1.kind::f16 [%0], %1, %2, %3, {%4, %4, %4, %4}, p;\n\t}"
        :: "r"(d), "l"(ad), "l"(bd), "r"(idesc), "r"(0u), "r"(en) : "memory");
}
__device__ __forceinline__ void tmem_ld32(uint32_t* r, uint32_t addr) {
    asm volatile(
        "tcgen05.ld.sync.aligned.32x32b.x32.b32 "
        "{%0,%1,%2,%3,%4,%5,%6,%7,%8,%9,%10,%11,%12,%13,%14,%15,"
        "%16,%17,%18,%19,%20,%21,%22,%23,%24,%25,%26,%27,%28,%29,%30,%31}, [%32];"
        : "=r"(r[0]), "=r"(r[1]), "=r"(r[2]), "=r"(r[3]),
          "=r"(r[4]), "=r"(r[5]), "=r"(r[6]), "=r"(r[7]),
          "=r"(r[8]), "=r"(r[9]), "=r"(r[10]), "=r"(r[11]),
          "=r"(r[12]), "=r"(r[13]), "=r"(r[14]), "=r"(r[15]),
          "=r"(r[16]), "=r"(r[17]), "=r"(r[18]), "=r"(r[19]),
          "=r"(r[20]), "=r"(r[21]), "=r"(r[22]), "=r"(r[23]),
          "=r"(r[24]), "=r"(r[25]), "=r"(r[26]), "=r"(r[27]),
          "=r"(r[28]), "=r"(r[29]), "=r"(r[30]), "=r"(r[31])
        : "r"(addr));
}
#define TC_WAIT_LD()      asm volatile("tcgen05.wait::ld.sync.aligned;" ::: "memory")
#define TC_FENCE_AFTER()  asm volatile("tcgen05.fence::after_thread_sync;" ::: "memory")
#define TC_FENCE_BEFORE() asm volatile("tcgen05.fence::before_thread_sync;" ::: "memory")
#define FENCE_ASYNC()     asm volatile("fence.proxy.async.shared::cta;" ::: "memory")
#endif  // TC_OK

#define SWZ(o) ((o) ^ (((o) >> 3) & 0x70))

__device__ __forceinline__ uint64_t mk_desc(uint32_t addr) {
    return (2ull << 61) | (1ull << 46) | (64ull << 32) | (1ull << 16)
         | ((uint64_t)(addr >> 4) & 0x3FFF);
}

// idesc: dtype=F32, a=BF16, b=BF16, N=256, M=128
static constexpr uint32_t IDESC =
    (1u << 4) | (1u << 7) | (1u << 10) | ((256u / 8) << 17) | ((128u / 16) << 24);

// SMEM layout (bytes from 1024-aligned base)
#define OFF_PTR   0
#define OFF_MB    16                   // chunk mbars @16,24; tile mbar @32
#define OFF_AH(s) (1024 + (s) * 32768)
#define OFF_AL(s) (1024 + (s) * 32768 + 16384)
#define OFF_BH(s) (66560 + (s) * 65536)
#define OFF_BL(s) (66560 + (s) * 65536 + 32768)
#define TG_SMEM   198656

// ---------------- small kernels ---------------------------------------------
__global__ void k_zero(uint32_t* p, int n) {
    int i = blockIdx.x * blockDim.x + threadIdx.x;
    if (i < n) p[i] = 0u;
}

__device__ __forceinline__ void bsplit(float w, __nv_bfloat16* H, __nv_bfloat16* L, int i) {
    __nv_bfloat16 h = __float2bfloat16(w);
    H[i] = h;
    L[i] = __float2bfloat16(w - __bfloat162float(h));
}

__global__ void k_pack(const float* __restrict__ Wz, const float* __restrict__ Wh,
                       const float* __restrict__ Ur, const float* __restrict__ Ow,
                       const int* __restrict__ fnode, const int* __restrict__ fmess,
                       int* __restrict__ mx) {
    int i = blockIdx.x * blockDim.x + threadIdx.x;
    int st = gridDim.x * blockDim.x;
    for (int t = i; t < 256 * 256; t += st) {
        int n = t >> 8, k = t & 255;
        bsplit(Ur[k * 256 + n],         g_BUh, g_BUl, t);
        bsplit(Wz[(256 + k) * 256 + n], g_BZh, g_BZl, t);
        bsplit(Wh[(256 + k) * 256 + n], g_BHh, g_BHl, t);
        bsplit(Ow[(256 + k) * 256 + n], g_BOh, g_BOl, t);
    }
    for (int t = i; t < M_MSG; t += st) mx[t] = fnode[fmess[t]];
}

// EX/EO tables: per-vocab precompute of all x-dependent matmuls.
__global__ void k_prep(const float* __restrict__ emb,
                       const float* __restrict__ Wz, const float* __restrict__ Wh,
                       const float* __restrict__ Wr, const float* __restrict__ Ow,
                       const float* __restrict__ Wzb, const float* __restrict__ Whb,
                       const float* __restrict__ Urb, const float* __restrict__ Ob,
                       float* __restrict__ EX, float* __restrict__ EO) {
    __shared__ float e[256];
    int v = blockIdx.x, j = threadIdx.x;
    e[j] = emb[v * 256 + j];
    __syncthreads();
    float s0 = 0, s1 = 0, s2 = 0, s3 = 0;
#pragma unroll 4
    for (int k = 0; k < 256; k++) {
        float ek = e[k];
        s0 = fmaf(ek, Wz[k * 256 + j], s0);
        s1 = fmaf(ek, Wh[k * 256 + j], s1);
        s2 = fmaf(ek, Wr[k * 256 + j], s2);
        s3 = fmaf(ek, Ow[k * 256 + j], s3);
    }
    EX[v * 768 + j]       = s0 + Wzb[j];
    EX[v * 768 + 256 + j] = s1 + Whb[j];
    EX[v * 768 + 512 + j] = s2 + Urb[j];
    EO[v * 256 + j]       = s3 + Ob[j];
}

// Gather: sum_h (packed) and sum_gh (packed). 64 thr/msg.
__global__ void k_gather(const int* __restrict__ mg, const uint32_t* __restrict__ hpk,
                         const __nv_bfloat16* __restrict__ Ub,
                         const float* __restrict__ EX, const int* __restrict__ mx,
                         uint32_t* __restrict__ shp, uint32_t* __restrict__ sgp) {
    int gt = blockIdx.x * blockDim.x + threadIdx.x;
    int msg = gt >> 6;
    int j = gt & 63;
    if (msg >= M_MSG) return;
    int mxv = __ldg(mx + msg);
    float4 r1 = *(const float4*)(EX + (size_t)mxv * 768 + 512 + j * 4);
    float sh0 = 0, sh1 = 0, sh2 = 0, sh3 = 0;
    float sg0 = 0, sg1 = 0, sg2 = 0, sg3 = 0;
    const uint4* h4 = (const uint4*)hpk;
#pragma unroll
    for (int k = 0; k < 5; k++) {
        int gi = __ldg(mg + msg * 5 + k);
        uint4 hp = h4[(size_t)gi * 64 + j];
        float h0 = pk_dec(hp.x), h1 = pk_dec(hp.y), h2 = pk_dec(hp.z), h3 = pk_dec(hp.w);
        uint2 uu = *(const uint2*)(Ub + (size_t)gi * 256 + j * 4);
        sh0 += h0; sh1 += h1; sh2 += h2; sh3 += h3;
        sg0 += sgm(r1.x + bf_lo16(uu.x)) * h0;
        sg1 += sgm(r1.y + bf_hi16(uu.x)) * h1;
        sg2 += sgm(r1.z + bf_lo16(uu.y)) * h2;
        sg3 += sgm(r1.w + bf_hi16(uu.y)) * h3;
    }
    size_t o = (size_t)msg * 64 + j;
    ((uint4*)shp)[o] = make_uint4(pk_enc(sh0), pk_enc(sh1), pk_enc(sh2), pk_enc(sh3));
    ((uint4*)sgp)[o] = make_uint4(pk_enc(sg0), pk_enc(sg1), pk_enc(sg2), pk_enc(sg3));
}

// Per-node neighbor-message sum (packed in, packed out).
__global__ void k_gnode(const int* __restrict__ ng, const uint32_t* __restrict__ hpk,
                        uint32_t* __restrict__ mnp) {
    int gt = blockIdx.x * blockDim.x + threadIdx.x;
    int n = gt >> 6;
    int j = gt & 63;
    if (n >= NNODE) return;
    const uint4* h4 = (const uint4*)hpk;
    float x = 0, y = 0, z = 0, w = 0;
#pragma unroll
    for (int k = 0; k < 5; k++) {
        int gi = __ldg(ng + n * 5 + k);
        uint4 hp = h4[(size_t)gi * 64 + j];
        x += pk_dec(hp.x); y += pk_dec(hp.y); z += pk_dec(hp.z); w += pk_dec(hp.w);
    }
    ((uint4*)mnp)[(size_t)n * 64 + j] = make_uint4(pk_enc(x), pk_enc(y), pk_enc(z), pk_enc(w));
}

// Deterministic segment mean over sorted scope_ids.
__global__ void k_seg(const int* __restrict__ scope, const float* __restrict__ nv,
                      float* __restrict__ out) {
    int t = blockIdx.x;
    int j = threadIdx.x;
    int lo = 0, hi = NNODE;
    while (lo < hi) { int mid = (lo + hi) >> 1; if (scope[mid] < t) lo = mid + 1; else hi = mid; }
    int lo2 = lo, hi2 = NNODE;
    while (lo2 < hi2) { int mid = (lo2 + hi2) >> 1; if (scope[mid] < t + 1) lo2 = mid + 1; else hi2 = mid; }
    float s = 0.f;
    for (int r = lo; r < lo2; r++) s += nv[(size_t)r * HID + j];
    out[(size_t)t * HID + j] = s / fmaxf((float)(lo2 - lo), 1.f);
}

// ---------------- persistent tcgen05 GEMM, 128x256 tile, split accumulators -
// Per m-tile: D0 = Ah@Bh^T (TMEM 0-255), D1 = Ah@Bl^T + Al@Bh^T (TMEM 256-511).
// Epilogue combines v = D0 + D1 then applies MODE:
//   MODE 0 (U):  Ub = bf16(v)
//   MODE 1 (Z):  zu = u16(sigmoid(EXz[mx[m]] + v) * 65535)
//   MODE 2 (H):  h = (1-z)*sum_h + z*tanh(EXh[mx[m]] + v); mask row0; packed
//   MODE 3 (NV): nv = relu(EO[fn[m]] + v)
struct TG {
    const uint32_t* Apk;
    const __nv_bfloat16 *Bh, *Bl;    // [256][256]
    __nv_bfloat16* Ub;               // MODE 0 out
    unsigned short* zu;              // MODE 1 out / MODE 2 in
    const float* EX; const int* mx;  // MODE 1,2
    const uint32_t* shp;             // MODE 2 in
    uint32_t* hpk;                   // MODE 2 out
    const float* EO; const int* fn; float* nv;  // MODE 3
    int mT;
};

#if TC_OK
template <int MODE>
__device__ __forceinline__ void epi(const TG& p, uint32_t tmem, int m0, int tid) {
    int w = tid >> 5, l = tid & 31;
    int row = (w & 3) * 32 + l;
    int m = m0 + row;
    int chl = (w >> 2) * 128;
    int mxm = 0;
    if (MODE == 1 || MODE == 2) mxm = __ldg(p.mx + m);
    if (MODE == 3) mxm = __ldg(p.fn + m);
#pragma unroll 1
    for (int cb = 0; cb < 4; cb++) {
        int colloc = chl + cb * 32;
        uint32_t r0_[32], r1_[32];
        tmem_ld32(r0_, tmem + colloc);
        tmem_ld32(r1_, tmem + 256 + colloc);
        TC_WAIT_LD();
        float v[32];
#pragma unroll
        for (int i = 0; i < 32; i++)
            v[i] = __uint_as_float(r0_[i]) + __uint_as_float(r1_[i]);
        int col = colloc;
        if (MODE == 0) {
            uint4* dst = (uint4*)(p.Ub + (size_t)m * 256 + col);
#pragma unroll
            for (int i2 = 0; i2 < 4; i2++)
                dst[i2] = make_uint4(bf2pk(v[i2*8+0], v[i2*8+1]), bf2pk(v[i2*8+2], v[i2*8+3]),
                                     bf2pk(v[i2*8+4], v[i2*8+5]), bf2pk(v[i2*8+6], v[i2*8+7]));
        } else if (MODE == 1) {
            const float4* ex4 = (const float4*)(p.EX + (size_t)mxm * 768 + col);
            uint32_t zp[16];
#pragma unroll
            for (int j2 = 0; j2 < 8; j2++) {
                float4 ex = ex4[j2];
                uint32_t a = __float2uint_rn(sgm(ex.x + v[j2*4+0]) * 65535.f);
                uint32_t b = __float2uint_rn(sgm(ex.y + v[j2*4+1]) * 65535.f);
                uint32_t c = __float2uint_rn(sgm(ex.z + v[j2*4+2]) * 65535.f);
                uint32_t d = __float2uint_rn(sgm(ex.w + v[j2*4+3]) * 65535.f);
                zp[j2*2+0] = a | (b << 16);
                zp[j2*2+1] = c | (d << 16);
            }
            uint4* dst = (uint4*)(p.zu + (size_t)m * 256 + col);
#pragma unroll
            for (int i2 = 0; i2 < 4; i2++)
                dst[i2] = make_uint4(zp[i2*4+0], zp[i2*4+1], zp[i2*4+2], zp[i2*4+3]);
        } else if (MODE == 2) {
            const float4* xh4 = (const float4*)(p.EX + (size_t)mxm * 768 + 256 + col);
            const uint4* sp4 = (const uint4*)(p.shp + (size_t)m * 256 + col);
            const uint2* zp2 = (const uint2*)(p.zu + (size_t)m * 256 + col);
            uint4* hd = (uint4*)(p.hpk + (size_t)m * 256 + col);
            const float inv = 1.f / 65535.f;
#pragma unroll
            for (int j2 = 0; j2 < 8; j2++) {
                float4 xh = xh4[j2];
                uint4 sp = sp4[j2];
                uint2 zz = zp2[j2];
                float z0 = (float)(zz.x & 0xFFFF) * inv, z1 = (float)(zz.x >> 16) * inv;
                float z2 = (float)(zz.y & 0xFFFF) * inv, z3 = (float)(zz.y >> 16) * inv;
                float h0 = (1.f - z0) * pk_dec(sp.x) + z0 * tanhf(xh.x + v[j2*4+0]);
                float h1 = (1.f - z1) * pk_dec(sp.y) + z1 * tanhf(xh.y + v[j2*4+1]);
                float h2 = (1.f - z2) * pk_dec(sp.z) + z2 * tanhf(xh.z + v[j2*4+2]);
                float h3 = (1.f - z3) * pk_dec(sp.w) + z3 * tanhf(xh.w + v[j2*4+3]);
                if (m == 0) { h0 = h1 = h2 = h3 = 0.f; }
                hd[j2] = make_uint4(pk_enc(h0), pk_enc(h1), pk_enc(h2), pk_enc(h3));
            }
        } else {
            const float4* eo4 = (const float4*)(p.EO + (size_t)mxm * 256 + col);
            float4* dst = (float4*)(p.nv + (size_t)m * 256 + col);
#pragma unroll
            for (int j2 = 0; j2 < 8; j2++) {
                float4 eo = eo4[j2];
                dst[j2] = make_float4(fmaxf(eo.x + v[j2*4+0], 0.f),
                                      fmaxf(eo.y + v[j2*4+1], 0.f),
                                      fmaxf(eo.z + v[j2*4+2], 0.f),
                                      fmaxf(eo.w + v[j2*4+3], 0.f));
            }
        }
    }
    TC_FENCE_BEFORE();
}
#endif

template <int MODE>
__global__ void __launch_bounds__(256) tgemm(TG p) {
    extern __shared__ char smraw[];
    char* sm = (char*)(((uintptr_t)smraw + 1023) & ~(uintptr_t)1023);
    const int tid = threadIdx.x;
#if TC_OK
    uint32_t sb = su32(sm);
    if (tid < 32) tc_alloc(sb + OFF_PTR, 512);
    if (tid == 0) {
        mbar_init(sb + OFF_MB + 0, 1);
        mbar_init(sb + OFF_MB + 8, 1);
        mbar_init(sb + OFF_MB + 16, 1);
    }
    __syncthreads();
    uint32_t tmem = *(const uint32_t*)(sm + OFF_PTR);

    int gc = 0, ph0 = 0, ph1 = 0, tp = 0;
    for (int ti = blockIdx.x; ti < p.mT; ti += gridDim.x) {
        int m0 = ti * 128;
        for (int c = 0; c < 4; c++) {
            int s = gc & 1;
            if (gc >= 2) {
                if (s == 0) { mbar_wait(sb + OFF_MB + 0, ph0); ph0 ^= 1; }
                else        { mbar_wait(sb + OFF_MB + 8, ph1); ph1 ^= 1; }
            }
            // stage A chunk c: packed -> hi/lo bf16 tiles (PRMT decode), SW128
            {
                int q = tid & 15, r0 = tid >> 4;
                const uint4* Ag = (const uint4*)(p.Apk + (size_t)m0 * 256) + c * 16;
                char* dAh = sm + OFF_AH(s);
                char* dAl = sm + OFF_AL(s);
#pragma unroll
                for (int u = 0; u < 8; u++) {
                    int row = u * 16 + r0;
                    uint4 pk = Ag[(size_t)row * 64 + q];
                    uint32_t sw = SWZ((uint32_t)(row * 128 + q * 8));
                    *(uint2*)(dAh + sw) = make_uint2(__byte_perm(pk.x, pk.y, 0x7632),
                                                     __byte_perm(pk.z, pk.w, 0x7632));
                    *(uint2*)(dAl + sw) = make_uint2(__byte_perm(pk.x, pk.y, 0x5410),
                                                     __byte_perm(pk.z, pk.w, 0x5410));
                }
            }
            // stage B chunk c: all 256 n-rows, hi/lo, SW128 (L2-hot weights)
            {
                int q = tid & 7, r0 = tid >> 3;
                char* dBh = sm + OFF_BH(s);
                char* dBl = sm + OFF_BL(s);
#pragma unroll
                for (int u = 0; u < 8; u++) {
                    int row = u * 32 + r0;
                    size_t go = (size_t)row * 256 + c * 64 + q * 8;
                    uint32_t sw = SWZ((uint32_t)(row * 128 + q * 16));
                    *(uint4*)(dBh + sw) = *(const uint4*)(p.Bh + go);
                    *(uint4*)(dBl + sw) = *(const uint4*)(p.Bl + go);
                }
            }
            FENCE_ASYNC();
            __syncthreads();
            if (tid < 32 && elect1()) {
                uint64_t ah = mk_desc(sb + OFF_AH(s));
                uint64_t al = mk_desc(sb + OFF_AL(s));
                uint64_t bh = mk_desc(sb + OFF_BH(s));
                uint64_t bl = mk_desc(sb + OFF_BL(s));
#pragma unroll
                for (int k = 0; k < 4; k++) {
                    bool acc = (c > 0) || (k > 0);
                    mma_f16_ss(tmem,       ah + k * 2, bh + k * 2, IDESC, acc);
                    mma_f16_ss(tmem + 256, ah + k * 2, bl + k * 2, IDESC, acc);
                    mma_f16_ss(tmem + 256, al + k * 2, bh + k * 2, IDESC, true);
                }
                tc_commit(sb + OFF_MB + s * 8);
                if (c == 3) tc_commit(sb + OFF_MB + 16);
            }
            gc++;
        }
        mbar_wait(sb + OFF_MB + 16, tp); tp ^= 1;
        TC_FENCE_AFTER();
        epi<MODE>(p, tmem, m0, tid);
    }
    __syncthreads();
    if (tid < 32) tc_dealloc(tmem, 512);
#else
    // Compile-only fallback for the plain compute_103 PTX pass (never run:
    // exact sm_103a SASS is embedded in the fatbin and always preferred).
    for (int ti = blockIdx.x; ti < p.mT; ti += gridDim.x) {
        int m0 = ti * 128;
        for (int e = tid; e < 128 * 256; e += 256) {
            int r = e >> 8, col = e & 255;
            int m = m0 + r;
            float acc = 0.f;
            for (int k = 0; k < 256; k++) {
                float a = pk_dec(p.Apk[(size_t)m * 256 + k]);
                float b = __bfloat162float(p.Bh[(size_t)col * 256 + k])
                        + __bfloat162float(p.Bl[(size_t)col * 256 + k]);
                acc += a * b;
            }
            if (MODE == 0) {
                p.Ub[(size_t)m * 256 + col] = __float2bfloat16(acc);
            } else if (MODE == 1) {
                int mxm = p.mx[m];
                float z = sgm(p.EX[(size_t)mxm * 768 + col] + acc);
                p.zu[(size_t)m * 256 + col] =
                    (unsigned short)__float2uint_rn(z * 65535.f);
            } else if (MODE == 2) {
                int mxm = p.mx[m];
                float z = (float)p.zu[(size_t)m * 256 + col] * (1.f / 65535.f);
                float sh = pk_dec(p.shp[(size_t)m * 256 + col]);
                float h = (1.f - z) * sh
                        + z * tanhf(p.EX[(size_t)mxm * 768 + 256 + col] + acc);
                if (m == 0) h = 0.f;
                p.hpk[(size_t)m * 256 + col] = pk_enc(h);
            } else {
                int fn = p.fn[m];
                p.nv[(size_t)m * 256 + col] =
                    fmaxf(p.EO[(size_t)fn * 256 + col] + acc, 0.f);
            }
        }
    }
#endif
}

// ---------------- orchestration --------------------------------------------
extern "C" void kernel_launch(void* const* d_in, const int* in_sizes, int n_in,
                              void* d_out, int out_size) {
    const int*   fnode = (const int*)d_in[0];
    const int*   fmess = (const int*)d_in[1];
    const int*   ng    = (const int*)d_in[2];
    const int*   mg    = (const int*)d_in[3];
    const int*   scope = (const int*)d_in[4];
    const float* emb   = (const float*)d_in[5];
    const float* Wz    = (const float*)d_in[6];
    const float* Wzb   = (const float*)d_in[7];
    const float* Wr    = (const float*)d_in[8];
    const float* Ur    = (const float*)d_in[9];
    const float* Urb   = (const float*)d_in[10];
    const float* Wh    = (const float*)d_in[11];
    const float* Whb   = (const float*)d_in[12];
    const float* Ow    = (const float*)d_in[13];
    const float* Ob    = (const float*)d_in[14];
    float* out = (float*)d_out;

    uint32_t *hpk, *shp, *sgp, *mnp;
    unsigned short* zu;
    __nv_bfloat16 *Ub, *BUh, *BUl, *BZh, *BZl, *BHh, *BHl, *BOh, *BOl;
    float *nv, *EX, *EO;
    int* mx;
    cudaGetSymbolAddress((void**)&hpk, g_hpk);
    cudaGetSymbolAddress((void**)&shp, g_shp);
    cudaGetSymbolAddress((void**)&sgp, g_sgp);
    cudaGetSymbolAddress((void**)&zu,  g_zu);
    cudaGetSymbolAddress((void**)&Ub,  g_Ub);
    cudaGetSymbolAddress((void**)&mnp, g_mnp);
    cudaGetSymbolAddress((void**)&nv,  g_nv);
    cudaGetSymbolAddress((void**)&EX,  g_EX);
    cudaGetSymbolAddress((void**)&EO,  g_EO);
    cudaGetSymbolAddress((void**)&mx,  g_mx);
    cudaGetSymbolAddress((void**)&BUh, g_BUh); cudaGetSymbolAddress((void**)&BUl, g_BUl);
    cudaGetSymbolAddress((void**)&BZh, g_BZh); cudaGetSymbolAddress((void**)&BZl, g_BZl);
    cudaGetSymbolAddress((void**)&BHh, g_BHh); cudaGetSymbolAddress((void**)&BHl, g_BHl);
    cudaGetSymbolAddress((void**)&BOh, g_BOh); cudaGetSymbolAddress((void**)&BOl, g_BOl);

    cudaFuncSetAttribute(tgemm<0>, cudaFuncAttributeMaxDynamicSharedMemorySize, TG_SMEM);
    cudaFuncSetAttribute(tgemm<1>, cudaFuncAttributeMaxDynamicSharedMemorySize, TG_SMEM);
    cudaFuncSetAttribute(tgemm<2>, cudaFuncAttributeMaxDynamicSharedMemorySize, TG_SMEM);
    cudaFuncSetAttribute(tgemm<3>, cudaFuncAttributeMaxDynamicSharedMemorySize, TG_SMEM);

    k_zero<<<(M_MSG * 256) / 256, 256>>>(hpk, M_MSG * 256);
    k_pack<<<512, 256>>>(Wz, Wh, Ur, Ow, fnode, fmess, mx);
    k_prep<<<780, 256>>>(emb, Wz, Wh, Wr, Ow, Wzb, Whb, Urb, Ob, EX, EO);

    for (int d = 0; d < DEPTH; d++) {
        // Uh = h @ Ur   (bf16 out)
        TG pU{}; pU.Apk = hpk; pU.Bh = BUh; pU.Bl = BUl; pU.Ub = Ub;
        pU.mT = M_MSG / 128;
        tgemm<0><<<GRID_P, 256, TG_SMEM>>>(pU);
        // gather: sum_h, sum_gh
        k_gather<<<(M_MSG * 64) / 256, 256>>>(mg, hpk, Ub, EX, mx, shp, sgp);
        // z = sigmoid(EXz[mx] + sum_h @ Wzh)   (u16 out)
        TG pZ{}; pZ.Apk = shp; pZ.Bh = BZh; pZ.Bl = BZl; pZ.zu = zu;
        pZ.EX = EX; pZ.mx = mx; pZ.mT = M_MSG / 128;
        tgemm<1><<<GRID_P, 256, TG_SMEM>>>(pZ);
        // h = (1-z)*sum_h + z*tanh(EXh[mx] + sum_gh @ Whh), mask row0
        TG pH{}; pH.Apk = sgp; pH.Bh = BHh; pH.Bl = BHl;
        pH.EX = EX; pH.mx = mx; pH.zu = zu; pH.shp = shp; pH.hpk = hpk;
        pH.mT = M_MSG / 128;
        tgemm<2><<<GRID_P, 256, TG_SMEM>>>(pH);
    }

    // mess_nei per node (packed)
    k_gnode<<<(NNODE * 64) / 256, 256>>>(ng, hpk, mnp);

    // node_vec = relu(EO[fnode] + mn @ Ow2)
    TG pN{}; pN.Apk = mnp; pN.Bh = BOh; pN.Bl = BOl;
    pN.EO = EO; pN.fn = fnode; pN.nv = nv; pN.mT = NNODE / 128;
    tgemm<3><<<GRID_P, 256, TG_SMEM>>>(pN);

    // segment mean (sorted scopes, deterministic)
    k_seg<<<NTREE, 256>>>(scope, nv, out);
}

// round 11
// speedup vs baseline: 2.3008x; 1.7451x over previous
#include <cuda_runtime.h>
#include <cuda_bf16.h>
#include <cstdint>
#include <cstddef>

#define M_MSG 131072
#define NNODE 65536
#define HID   256
#define DEPTH 6
#define NTREE 2048
#define GRID_P 148

#if defined(__CUDA_ARCH_FEAT_SM103_ALL) || defined(__CUDA_ARCH_FEAT_SM100_ALL) || \
    defined(__CUDA_ARCH_FEAT_SM101_ALL) || defined(__CUDA_ARCH_FEAT_SM110_ALL)
#define TC_OK 1
#else
#define TC_OK 0
#endif

// ---------------- static device scratch ------------------------------------
// packed value = (bf16_hi_bits << 16) | bf16_lo_bits ; val = hi + lo
__device__ uint32_t g_hpk[(size_t)M_MSG * 256];     // h packed
__device__ uint32_t g_shp[(size_t)M_MSG * 256];     // sum_h packed
__device__ uint32_t g_sgp[(size_t)M_MSG * 256];     // sum_gh packed
__device__ unsigned short g_zu[(size_t)M_MSG * 256];// z gate u16 fixed point
__device__ __nv_bfloat16 g_Ub[(size_t)M_MSG * 256]; // Uh = h@Ur, bf16
__device__ uint32_t g_mnp[(size_t)NNODE * 256];     // mess_nei packed
__device__ float g_nv[(size_t)NNODE * 256];         // node_vec
__device__ float g_EX[780 * 768];                   // emb@[Wzx|Whx|Wr]+biases
__device__ float g_EO[780 * 256];                   // emb@Ow1+Ob
__device__ int   g_mx[M_MSG];                       // fnode[fmess[m]]
// bf16 hi/lo split weights, [n][k] layout (B operand = W^T), all 256x256
__device__ __nv_bfloat16 g_BUh[256 * 256], g_BUl[256 * 256];  // Ur^T
__device__ __nv_bfloat16 g_BZh[256 * 256], g_BZl[256 * 256];  // Wzh^T
__device__ __nv_bfloat16 g_BHh[256 * 256], g_BHl[256 * 256];  // Whh^T
__device__ __nv_bfloat16 g_BOh[256 * 256], g_BOl[256 * 256];  // Ow2^T

// ---------------- packed bf16-pair helpers ----------------------------------
__device__ __forceinline__ float pk_dec(uint32_t p) {
    return __uint_as_float(p & 0xFFFF0000u) + __uint_as_float(p << 16);
}
__device__ __forceinline__ uint32_t pk_enc(float v) {
    __nv_bfloat16 hb = __float2bfloat16(v);
    float lo = v - __bfloat162float(hb);
    return ((uint32_t)__bfloat16_as_ushort(hb) << 16)
         | (uint32_t)__bfloat16_as_ushort(__float2bfloat16(lo));
}
__device__ __forceinline__ float bf_lo16(uint32_t u) { return __uint_as_float(u << 16); }
__device__ __forceinline__ float bf_hi16(uint32_t u) { return __uint_as_float(u & 0xFFFF0000u); }
__device__ __forceinline__ uint32_t bf2pk(float a, float b) {
    return (uint32_t)__bfloat16_as_ushort(__float2bfloat16(a))
         | ((uint32_t)__bfloat16_as_ushort(__float2bfloat16(b)) << 16);
}
__device__ __forceinline__ float sgm(float x) { return 1.0f / (1.0f + __expf(-x)); }

// ---------------- PTX helpers ------------------------------------------------
__device__ __forceinline__ uint32_t su32(const void* p) {
    uint32_t a;
    asm("{ .reg .u64 t; cvta.to.shared.u64 t, %1; cvt.u32.u64 %0, t; }"
        : "=r"(a) : "l"(p));
    return a;
}
#if TC_OK
__device__ __forceinline__ bool elect1() {
    uint32_t p;
    asm volatile("{\n\t.reg .pred p;\n\telect.sync _|p, 0xFFFFFFFF;\n\t"
                 "selp.b32 %0, 1, 0, p;\n\t}" : "=r"(p));
    return p != 0;
}
__device__ __forceinline__ void mbar_init(uint32_t a, uint32_t cnt) {
    asm volatile("mbarrier.init.shared.b64 [%0], %1;" :: "r"(a), "r"(cnt) : "memory");
}
__device__ __forceinline__ void mbar_wait(uint32_t a, int par) {
    asm volatile(
        "{\n\t.reg .pred P;\n"
        "W%=:\n\t"
        "mbarrier.try_wait.parity.acquire.cta.shared::cta.b64 P, [%0], %1, 0x989680;\n\t"
        "@P bra.uni D%=;\n\t"
        "bra.uni W%=;\n"
        "D%=:\n\t}" :: "r"(a), "r"(par) : "memory");
}
__device__ __forceinline__ void tc_alloc(uint32_t smem_res, uint32_t ncols) {
    asm volatile("tcgen05.alloc.cta_group::1.sync.aligned.shared::cta.b32 [%0], %1;"
                 :: "r"(smem_res), "r"(ncols) : "memory");
}
__device__ __forceinline__ void tc_dealloc(uint32_t tmem, uint32_t ncols) {
    asm volatile("tcgen05.dealloc.cta_group::1.sync.aligned.b32 %0, %1;"
                 :: "r"(tmem), "r"(ncols));
}
__device__ __forceinline__ void tc_commit(uint32_t mbar) {
    asm volatile("tcgen05.commit.cta_group::1.mbarrier::arrive::one.shared::cluster.b64 [%0];"
                 :: "r"(mbar) : "memory");
}
__device__ __forceinline__ void mma_f16_ss(uint32_t d, uint64_t ad, uint64_t bd,
                                           uint32_t idesc, bool acc) {
    uint32_t en = acc ? 1u : 0u;
    asm volatile(
        "{\n\t.reg .pred p;\n\tsetp.ne.u32 p, %5, 0;\n\t"
        "tcgen05.mma.cta_group::1.kind::f16 [%0], %1, %2, %3, {%4, %4, %4, %4}, p;\n\t}"
        :: "r"(d), "l"(ad), "l"(bd), "r"(idesc), "r"(0u), "r"(en) : "memory");
}
__device__ __forceinline__ void tmem_ld32(uint32_t* r, uint32_t addr) {
    asm volatile(
        "tcgen05.ld.sync.aligned.32x32b.x32.b32 "
        "{%0,%1,%2,%3,%4,%5,%6,%7,%8,%9,%10,%11,%12,%13,%14,%15,"
        "%16,%17,%18,%19,%20,%21,%22,%23,%24,%25,%26,%27,%28,%29,%30,%31}, [%32];"
        : "=r"(r[0]), "=r"(r[1]), "=r"(r[2]), "=r"(r[3]),
          "=r"(r[4]), "=r"(r[5]), "=r"(r[6]), "=r"(r[7]),
          "=r"(r[8]), "=r"(r[9]), "=r"(r[10]), "=r"(r[11]),
          "=r"(r[12]), "=r"(r[13]), "=r"(r[14]), "=r"(r[15]),
          "=r"(r[16]), "=r"(r[17]), "=r"(r[18]), "=r"(r[19]),
          "=r"(r[20]), "=r"(r[21]), "=r"(r[22]), "=r"(r[23]),
          "=r"(r[24]), "=r"(r[25]), "=r"(r[26]), "=r"(r[27]),
          "=r"(r[28]), "=r"(r[29]), "=r"(r[30]), "=r"(r[31])
        : "r"(addr));
}
__device__ __forceinline__ void cp16(uint32_t dst, const void* src) {
    asm volatile("cp.async.cg.shared.global [%0], [%1], 16;"
                 :: "r"(dst), "l"(src) : "memory");
}
#define CP_COMMIT()      asm volatile("cp.async.commit_group;" ::: "memory")
#define CP_WAIT(n)       asm volatile("cp.async.wait_group %0;" :: "n"(n) : "memory")
#define TC_WAIT_LD()      asm volatile("tcgen05.wait::ld.sync.aligned;" ::: "memory")
#define TC_FENCE_AFTER()  asm volatile("tcgen05.fence::after_thread_sync;" ::: "memory")
#define TC_FENCE_BEFORE() asm volatile("tcgen05.fence::before_thread_sync;" ::: "memory")
#define FENCE_ASYNC()     asm volatile("fence.proxy.async.shared::cta;" ::: "memory")
#endif  // TC_OK

#define SWZ(o) ((o) ^ (((o) >> 3) & 0x70))

__device__ __forceinline__ uint64_t mk_desc(uint32_t addr) {
    return (2ull << 61) | (1ull << 46) | (64ull << 32) | (1ull << 16)
         | ((uint64_t)(addr >> 4) & 0x3FFF);
}

// idesc: dtype=F32, a=BF16, b=BF16, N=256, M=128
static constexpr uint32_t IDESC =
    (1u << 4) | (1u << 7) | (1u << 10) | ((256u / 8) << 17) | ((128u / 16) << 24);

// SMEM layout (bytes from 1024-aligned base)
#define OFF_PTR   0
#define OFF_MB    16          // chunk mbars @16,24; tile mbars @32,40
#define OFF_AH(s) (1024 + (s) * 32768)
#define OFF_AL(s) (1024 + (s) * 32768 + 16384)
#define OFF_BH(s) (66560 + (s) * 65536)
#define OFF_BL(s) (66560 + (s) * 65536 + 32768)
#define TG_SMEM   198656

// ---------------- small kernels ---------------------------------------------
__global__ void k_zero(uint32_t* p, int n) {
    int i = blockIdx.x * blockDim.x + threadIdx.x;
    if (i < n) p[i] = 0u;
}

__device__ __forceinline__ void bsplit(float w, __nv_bfloat16* H, __nv_bfloat16* L, int i) {
    __nv_bfloat16 h = __float2bfloat16(w);
    H[i] = h;
    L[i] = __float2bfloat16(w - __bfloat162float(h));
}

__global__ void k_pack(const float* __restrict__ Wz, const float* __restrict__ Wh,
                       const float* __restrict__ Ur, const float* __restrict__ Ow,
                       const int* __restrict__ fnode, const int* __restrict__ fmess,
                       int* __restrict__ mx) {
    int i = blockIdx.x * blockDim.x + threadIdx.x;
    int st = gridDim.x * blockDim.x;
    for (int t = i; t < 256 * 256; t += st) {
        int n = t >> 8, k = t & 255;
        bsplit(Ur[k * 256 + n],         g_BUh, g_BUl, t);
        bsplit(Wz[(256 + k) * 256 + n], g_BZh, g_BZl, t);
        bsplit(Wh[(256 + k) * 256 + n], g_BHh, g_BHl, t);
        bsplit(Ow[(256 + k) * 256 + n], g_BOh, g_BOl, t);
    }
    for (int t = i; t < M_MSG; t += st) mx[t] = fnode[fmess[t]];
}

// EX/EO tables: per-vocab precompute of all x-dependent matmuls.
__global__ void k_prep(const float* __restrict__ emb,
                       const float* __restrict__ Wz, const float* __restrict__ Wh,
                       const float* __restrict__ Wr, const float* __restrict__ Ow,
                       const float* __restrict__ Wzb, const float* __restrict__ Whb,
                       const float* __restrict__ Urb, const float* __restrict__ Ob,
                       float* __restrict__ EX, float* __restrict__ EO) {
    __shared__ float e[256];
    int v = blockIdx.x, j = threadIdx.x;
    e[j] = emb[v * 256 + j];
    __syncthreads();
    float s0 = 0, s1 = 0, s2 = 0, s3 = 0;
#pragma unroll 4
    for (int k = 0; k < 256; k++) {
        float ek = e[k];
        s0 = fmaf(ek, Wz[k * 256 + j], s0);
        s1 = fmaf(ek, Wh[k * 256 + j], s1);
        s2 = fmaf(ek, Wr[k * 256 + j], s2);
        s3 = fmaf(ek, Ow[k * 256 + j], s3);
    }
    EX[v * 768 + j]       = s0 + Wzb[j];
    EX[v * 768 + 256 + j] = s1 + Whb[j];
    EX[v * 768 + 512 + j] = s2 + Urb[j];
    EO[v * 256 + j]       = s3 + Ob[j];
}

// Gather: sum_h (packed) and sum_gh (packed). 64 thr/msg.
__global__ void k_gather(const int* __restrict__ mg, const uint32_t* __restrict__ hpk,
                         const __nv_bfloat16* __restrict__ Ub,
                         const float* __restrict__ EX, const int* __restrict__ mx,
                         uint32_t* __restrict__ shp, uint32_t* __restrict__ sgp) {
    int gt = blockIdx.x * blockDim.x + threadIdx.x;
    int msg = gt >> 6;
    int j = gt & 63;
    if (msg >= M_MSG) return;
    int mxv = __ldg(mx + msg);
    float4 r1 = *(const float4*)(EX + (size_t)mxv * 768 + 512 + j * 4);
    float sh0 = 0, sh1 = 0, sh2 = 0, sh3 = 0;
    float sg0 = 0, sg1 = 0, sg2 = 0, sg3 = 0;
    const uint4* h4 = (const uint4*)hpk;
#pragma unroll
    for (int k = 0; k < 5; k++) {
        int gi = __ldg(mg + msg * 5 + k);
        uint4 hp = h4[(size_t)gi * 64 + j];
        float h0 = pk_dec(hp.x), h1 = pk_dec(hp.y), h2 = pk_dec(hp.z), h3 = pk_dec(hp.w);
        uint2 uu = *(const uint2*)(Ub + (size_t)gi * 256 + j * 4);
        sh0 += h0; sh1 += h1; sh2 += h2; sh3 += h3;
        sg0 += sgm(r1.x + bf_lo16(uu.x)) * h0;
        sg1 += sgm(r1.y + bf_hi16(uu.x)) * h1;
        sg2 += sgm(r1.z + bf_lo16(uu.y)) * h2;
        sg3 += sgm(r1.w + bf_hi16(uu.y)) * h3;
    }
    size_t o = (size_t)msg * 64 + j;
    ((uint4*)shp)[o] = make_uint4(pk_enc(sh0), pk_enc(sh1), pk_enc(sh2), pk_enc(sh3));
    ((uint4*)sgp)[o] = make_uint4(pk_enc(sg0), pk_enc(sg1), pk_enc(sg2), pk_enc(sg3));
}

// Per-node neighbor-message sum (packed in, packed out).
__global__ void k_gnode(const int* __restrict__ ng, const uint32_t* __restrict__ hpk,
                        uint32_t* __restrict__ mnp) {
    int gt = blockIdx.x * blockDim.x + threadIdx.x;
    int n = gt >> 6;
    int j = gt & 63;
    if (n >= NNODE) return;
    const uint4* h4 = (const uint4*)hpk;
    float x = 0, y = 0, z = 0, w = 0;
#pragma unroll
    for (int k = 0; k < 5; k++) {
        int gi = __ldg(ng + n * 5 + k);
        uint4 hp = h4[(size_t)gi * 64 + j];
        x += pk_dec(hp.x); y += pk_dec(hp.y); z += pk_dec(hp.z); w += pk_dec(hp.w);
    }
    ((uint4*)mnp)[(size_t)n * 64 + j] = make_uint4(pk_enc(x), pk_enc(y), pk_enc(z), pk_enc(w));
}

// Deterministic segment mean over sorted scope_ids.
__global__ void k_seg(const int* __restrict__ scope, const float* __restrict__ nv,
                      float* __restrict__ out) {
    int t = blockIdx.x;
    int j = threadIdx.x;
    int lo = 0, hi = NNODE;
    while (lo < hi) { int mid = (lo + hi) >> 1; if (scope[mid] < t) lo = mid + 1; else hi = mid; }
    int lo2 = lo, hi2 = NNODE;
    while (lo2 < hi2) { int mid = (lo2 + hi2) >> 1; if (scope[mid] < t + 1) lo2 = mid + 1; else hi2 = mid; }
    float s = 0.f;
    for (int r = lo; r < lo2; r++) s += nv[(size_t)r * HID + j];
    out[(size_t)t * HID + j] = s / fmaxf((float)(lo2 - lo), 1.f);
}

// ---------------- persistent tcgen05 GEMM, 128x256 tile ---------------------
// Single fp32 accumulator D (256 TMEM cols), ping-pong per tile (0 / 256).
// Per K64 chunk: 12 MMAs (hh, lh, hl per K16 step). Deferred epilogue:
// epilogue of tile i runs while tile i+1's MMAs are queued.
//   MODE 0 (U):  Ub = bf16(v)
//   MODE 1 (Z):  zu = u16(sigmoid(EXz[mx[m]] + v) * 65535)
//   MODE 2 (H):  h = (1-z)*sum_h + z*tanh(EXh[mx[m]] + v); mask row0; packed
//   MODE 3 (NV): nv = relu(EO[fn[m]] + v)
struct TG {
    const uint32_t* Apk;
    const __nv_bfloat16 *Bh, *Bl;    // [256][256]
    __nv_bfloat16* Ub;               // MODE 0 out
    unsigned short* zu;              // MODE 1 out / MODE 2 in
    const float* EX; const int* mx;  // MODE 1,2
    const uint32_t* shp;             // MODE 2 in
    uint32_t* hpk;                   // MODE 2 out
    const float* EO; const int* fn; float* nv;  // MODE 3
    int mT;
};

#if TC_OK
template <int MODE>
__device__ __forceinline__ void epi(const TG& p, uint32_t dbase, int m0, int tid) {
    int w = tid >> 5, l = tid & 31;
    int row = (w & 3) * 32 + l;
    int m = m0 + row;
    int chl = (w >> 2) * 128;
    int mxm = 0;
    if (MODE == 1 || MODE == 2) mxm = __ldg(p.mx + m);
    if (MODE == 3) mxm = __ldg(p.fn + m);
#pragma unroll 1
    for (int cb = 0; cb < 4; cb++) {
        int col = chl + cb * 32;
        uint32_t rr[32];
        tmem_ld32(rr, dbase + col);
        TC_WAIT_LD();
        float v[32];
#pragma unroll
        for (int i = 0; i < 32; i++) v[i] = __uint_as_float(rr[i]);
        if (MODE == 0) {
            uint4* dst = (uint4*)(p.Ub + (size_t)m * 256 + col);
#pragma unroll
            for (int i2 = 0; i2 < 4; i2++)
                dst[i2] = make_uint4(bf2pk(v[i2*8+0], v[i2*8+1]), bf2pk(v[i2*8+2], v[i2*8+3]),
                                     bf2pk(v[i2*8+4], v[i2*8+5]), bf2pk(v[i2*8+6], v[i2*8+7]));
        } else if (MODE == 1) {
            const float4* ex4 = (const float4*)(p.EX + (size_t)mxm * 768 + col);
            uint32_t zp[16];
#pragma unroll
            for (int j2 = 0; j2 < 8; j2++) {
                float4 ex = ex4[j2];
                uint32_t a = __float2uint_rn(sgm(ex.x + v[j2*4+0]) * 65535.f);
                uint32_t b = __float2uint_rn(sgm(ex.y + v[j2*4+1]) * 65535.f);
                uint32_t c = __float2uint_rn(sgm(ex.z + v[j2*4+2]) * 65535.f);
                uint32_t d = __float2uint_rn(sgm(ex.w + v[j2*4+3]) * 65535.f);
                zp[j2*2+0] = a | (b << 16);
                zp[j2*2+1] = c | (d << 16);
            }
            uint4* dst = (uint4*)(p.zu + (size_t)m * 256 + col);
#pragma unroll
            for (int i2 = 0; i2 < 4; i2++)
                dst[i2] = make_uint4(zp[i2*4+0], zp[i2*4+1], zp[i2*4+2], zp[i2*4+3]);
        } else if (MODE == 2) {
            const float4* xh4 = (const float4*)(p.EX + (size_t)mxm * 768 + 256 + col);
            const uint4* sp4 = (const uint4*)(p.shp + (size_t)m * 256 + col);
            const uint2* zp2 = (const uint2*)(p.zu + (size_t)m * 256 + col);
            uint4* hd = (uint4*)(p.hpk + (size_t)m * 256 + col);
            const float inv = 1.f / 65535.f;
#pragma unroll
            for (int j2 = 0; j2 < 8; j2++) {
                float4 xh = xh4[j2];
                uint4 sp = sp4[j2];
                uint2 zz = zp2[j2];
                float z0 = (float)(zz.x & 0xFFFF) * inv, z1 = (float)(zz.x >> 16) * inv;
                float z2 = (float)(zz.y & 0xFFFF) * inv, z3 = (float)(zz.y >> 16) * inv;
                float h0 = (1.f - z0) * pk_dec(sp.x) + z0 * tanhf(xh.x + v[j2*4+0]);
                float h1 = (1.f - z1) * pk_dec(sp.y) + z1 * tanhf(xh.y + v[j2*4+1]);
                float h2 = (1.f - z2) * pk_dec(sp.z) + z2 * tanhf(xh.z + v[j2*4+2]);
                float h3 = (1.f - z3) * pk_dec(sp.w) + z3 * tanhf(xh.w + v[j2*4+3]);
                if (m == 0) { h0 = h1 = h2 = h3 = 0.f; }
                hd[j2] = make_uint4(pk_enc(h0), pk_enc(h1), pk_enc(h2), pk_enc(h3));
            }
        } else {
            const float4* eo4 = (const float4*)(p.EO + (size_t)mxm * 256 + col);
            float4* dst = (float4*)(p.nv + (size_t)m * 256 + col);
#pragma unroll
            for (int j2 = 0; j2 < 8; j2++) {
                float4 eo = eo4[j2];
                dst[j2] = make_float4(fmaxf(eo.x + v[j2*4+0], 0.f),
                                      fmaxf(eo.y + v[j2*4+1], 0.f),
                                      fmaxf(eo.z + v[j2*4+2], 0.f),
                                      fmaxf(eo.w + v[j2*4+3], 0.f));
            }
        }
    }
    TC_FENCE_BEFORE();
}
#endif

template <int MODE>
__global__ void __launch_bounds__(256) tgemm(TG p) {
    extern __shared__ char smraw[];
    char* sm = (char*)(((uintptr_t)smraw + 1023) & ~(uintptr_t)1023);
    const int tid = threadIdx.x;
#if TC_OK
    uint32_t sb = su32(sm);
    if (tid < 32) tc_alloc(sb + OFF_PTR, 512);
    if (tid == 0) {
        mbar_init(sb + OFF_MB + 0, 1);  mbar_init(sb + OFF_MB + 8, 1);
        mbar_init(sb + OFF_MB + 16, 1); mbar_init(sb + OFF_MB + 24, 1);
    }
    __syncthreads();
    uint32_t tmem = *(const uint32_t*)(sm + OFF_PTR);

    // staging thread roles
    const int aq = tid & 15, ar = tid >> 4;       // A: 8 rows x 1 uint4
    const int bq = tid & 7,  br = tid >> 3;       // B: 8 rows x 2 cp.async

    int ph0 = 0, ph1 = 0, pend0 = 0, pend1 = 0;
    int tp0 = 0, tp1 = 0;
    int prev_m0 = -1, prev_db = 0;
    int lc = 0;

    for (int ti = blockIdx.x; ti < p.mT; ti += gridDim.x, lc++) {
        int m0 = ti * 128;
        int db = lc & 1;
        for (int c = 0; c < 4; c++) {
            int s = c & 1;
            if (s == 0) { if (pend0) { mbar_wait(sb + OFF_MB + 0, ph0); ph0 ^= 1; pend0 = 0; } }
            else        { if (pend1) { mbar_wait(sb + OFF_MB + 8, ph1); ph1 ^= 1; pend1 = 0; } }
            // A chunk: hoist all 8 LDG.128s, then PRMT-decode + STS
            uint4 av[8];
            {
                const uint4* Ag = (const uint4*)(p.Apk + (size_t)m0 * 256) + c * 16;
#pragma unroll
                for (int u = 0; u < 8; u++)
                    av[u] = Ag[(size_t)(u * 16 + ar) * 64 + aq];
            }
            // B chunk via cp.async (pure copies, latency hidden)
            {
                const __nv_bfloat16* Bhg = p.Bh + c * 64;
                const __nv_bfloat16* Blg = p.Bl + c * 64;
#pragma unroll
                for (int u = 0; u < 8; u++) {
                    int row = u * 32 + br;
                    size_t go = (size_t)row * 256 + bq * 8;
                    uint32_t sw = SWZ((uint32_t)(row * 128 + bq * 16));
                    cp16(sb + OFF_BH(s) + sw, Bhg + go);
                    cp16(sb + OFF_BL(s) + sw, Blg + go);
                }
            }
            CP_COMMIT();
            // A decode + store (overlaps LDG latency with cp issue above)
            {
                char* dAh = sm + OFF_AH(s);
                char* dAl = sm + OFF_AL(s);
#pragma unroll
                for (int u = 0; u < 8; u++) {
                    int row = u * 16 + ar;
                    uint32_t sw = SWZ((uint32_t)(row * 128 + aq * 8));
                    *(uint2*)(dAh + sw) = make_uint2(__byte_perm(av[u].x, av[u].y, 0x7632),
                                                     __byte_perm(av[u].z, av[u].w, 0x7632));
                    *(uint2*)(dAl + sw) = make_uint2(__byte_perm(av[u].x, av[u].y, 0x5410),
                                                     __byte_perm(av[u].z, av[u].w, 0x5410));
                }
            }
            if (c >= 1) {
                CP_WAIT(1);
                __syncthreads();
                FENCE_ASYNC();
                int sp = s ^ 1;   // buffer of chunk c-1
                if (tid < 32 && elect1()) {
                    uint64_t ah = mk_desc(sb + OFF_AH(sp));
                    uint64_t al = mk_desc(sb + OFF_AL(sp));
                    uint64_t bh = mk_desc(sb + OFF_BH(sp));
                    uint64_t bl = mk_desc(sb + OFF_BL(sp));
                    uint32_t d = tmem + db * 256;
#pragma unroll
                    for (int k = 0; k < 4; k++) {
                        bool acc = (c > 1) || (k > 0);
                        mma_f16_ss(d, ah + k * 2, bh + k * 2, IDESC, acc);
                        mma_f16_ss(d, al + k * 2, bh + k * 2, IDESC, true);
                        mma_f16_ss(d, ah + k * 2, bl + k * 2, IDESC, true);
                    }
                    tc_commit(sb + OFF_MB + sp * 8);
                }
                if (sp) pend1 = 1; else pend0 = 1;
            }
        }
        // tail: MMA of chunk 3 (buffer 1)
        CP_WAIT(0);
        __syncthreads();
        FENCE_ASYNC();
        if (tid < 32 && elect1()) {
            uint64_t ah = mk_desc(sb + OFF_AH(1));
            uint64_t al = mk_desc(sb + OFF_AL(1));
            uint64_t bh = mk_desc(sb + OFF_BH(1));
            uint64_t bl = mk_desc(sb + OFF_BL(1));
            uint32_t d = tmem + db * 256;
#pragma unroll
            for (int k = 0; k < 4; k++) {
                mma_f16_ss(d, ah + k * 2, bh + k * 2, IDESC, true);
                mma_f16_ss(d, al + k * 2, bh + k * 2, IDESC, true);
                mma_f16_ss(d, ah + k * 2, bl + k * 2, IDESC, true);
            }
            tc_commit(sb + OFF_MB + 8);
            tc_commit(sb + OFF_MB + 16 + db * 8);
        }
        pend1 = 1;
        // deferred epilogue of previous tile (overlaps this tile's MMAs)
        if (prev_m0 >= 0) {
            if (prev_db == 0) { mbar_wait(sb + OFF_MB + 16, tp0); tp0 ^= 1; }
            else              { mbar_wait(sb + OFF_MB + 24, tp1); tp1 ^= 1; }
            TC_FENCE_AFTER();
            epi<MODE>(p, tmem + prev_db * 256, prev_m0, tid);
        }
        prev_m0 = m0; prev_db = db;
    }
    if (prev_m0 >= 0) {
        if (prev_db == 0) { mbar_wait(sb + OFF_MB + 16, tp0); tp0 ^= 1; }
        else              { mbar_wait(sb + OFF_MB + 24, tp1); tp1 ^= 1; }
        TC_FENCE_AFTER();
        epi<MODE>(p, tmem + prev_db * 256, prev_m0, tid);
    }
    __syncthreads();
    if (tid < 32) tc_dealloc(tmem, 512);
#else
    // Compile-only fallback for the plain compute_103 PTX pass (never run:
    // exact sm_103a SASS is embedded in the fatbin and always preferred).
    for (int ti = blockIdx.x; ti < p.mT; ti += gridDim.x) {
        int m0 = ti * 128;
        for (int e = tid; e < 128 * 256; e += 256) {
            int r = e >> 8, col = e & 255;
            int m = m0 + r;
            float acc = 0.f;
            for (int k = 0; k < 256; k++) {
                float a = pk_dec(p.Apk[(size_t)m * 256 + k]);
                float b = __bfloat162float(p.Bh[(size_t)col * 256 + k])
                        + __bfloat162float(p.Bl[(size_t)col * 256 + k]);
                acc += a * b;
            }
            if (MODE == 0) {
                p.Ub[(size_t)m * 256 + col] = __float2bfloat16(acc);
            } else if (MODE == 1) {
                int mxm = p.mx[m];
                float z = sgm(p.EX[(size_t)mxm * 768 + col] + acc);
                p.zu[(size_t)m * 256 + col] =
                    (unsigned short)__float2uint_rn(z * 65535.f);
            } else if (MODE == 2) {
                int mxm = p.mx[m];
                float z = (float)p.zu[(size_t)m * 256 + col] * (1.f / 65535.f);
                float sh = pk_dec(p.shp[(size_t)m * 256 + col]);
                float h = (1.f - z) * sh
                        + z * tanhf(p.EX[(size_t)mxm * 768 + 256 + col] + acc);
                if (m == 0) h = 0.f;
                p.hpk[(size_t)m * 256 + col] = pk_enc(h);
            } else {
                int fn = p.fn[m];
                p.nv[(size_t)m * 256 + col] =
                    fmaxf(p.EO[(size_t)fn * 256 + col] + acc, 0.f);
            }
        }
    }
#endif
}

// ---------------- orchestration --------------------------------------------
extern "C" void kernel_launch(void* const* d_in, const int* in_sizes, int n_in,
                              void* d_out, int out_size) {
    const int*   fnode = (const int*)d_in[0];
    const int*   fmess = (const int*)d_in[1];
    const int*   ng    = (const int*)d_in[2];
    const int*   mg    = (const int*)d_in[3];
    const int*   scope = (const int*)d_in[4];
    const float* emb   = (const float*)d_in[5];
    const float* Wz    = (const float*)d_in[6];
    const float* Wzb   = (const float*)d_in[7];
    const float* Wr    = (const float*)d_in[8];
    const float* Ur    = (const float*)d_in[9];
    const float* Urb   = (const float*)d_in[10];
    const float* Wh    = (const float*)d_in[11];
    const float* Whb   = (const float*)d_in[12];
    const float* Ow    = (const float*)d_in[13];
    const float* Ob    = (const float*)d_in[14];
    float* out = (float*)d_out;

    uint32_t *hpk, *shp, *sgp, *mnp;
    unsigned short* zu;
    __nv_bfloat16 *Ub, *BUh, *BUl, *BZh, *BZl, *BHh, *BHl, *BOh, *BOl;
    float *nv, *EX, *EO;
    int* mx;
    cudaGetSymbolAddress((void**)&hpk, g_hpk);
    cudaGetSymbolAddress((void**)&shp, g_shp);
    cudaGetSymbolAddress((void**)&sgp, g_sgp);
    cudaGetSymbolAddress((void**)&zu,  g_zu);
    cudaGetSymbolAddress((void**)&Ub,  g_Ub);
    cudaGetSymbolAddress((void**)&mnp, g_mnp);
    cudaGetSymbolAddress((void**)&nv,  g_nv);
    cudaGetSymbolAddress((void**)&EX,  g_EX);
    cudaGetSymbolAddress((void**)&EO,  g_EO);
    cudaGetSymbolAddress((void**)&mx,  g_mx);
    cudaGetSymbolAddress((void**)&BUh, g_BUh); cudaGetSymbolAddress((void**)&BUl, g_BUl);
    cudaGetSymbolAddress((void**)&BZh, g_BZh); cudaGetSymbolAddress((void**)&BZl, g_BZl);
    cudaGetSymbolAddress((void**)&BHh, g_BHh); cudaGetSymbolAddress((void**)&BHl, g_BHl);
    cudaGetSymbolAddress((void**)&BOh, g_BOh); cudaGetSymbolAddress((void**)&BOl, g_BOl);

    cudaFuncSetAttribute(tgemm<0>, cudaFuncAttributeMaxDynamicSharedMemorySize, TG_SMEM);
    cudaFuncSetAttribute(tgemm<1>, cudaFuncAttributeMaxDynamicSharedMemorySize, TG_SMEM);
    cudaFuncSetAttribute(tgemm<2>, cudaFuncAttributeMaxDynamicSharedMemorySize, TG_SMEM);
    cudaFuncSetAttribute(tgemm<3>, cudaFuncAttributeMaxDynamicSharedMemorySize, TG_SMEM);

    k_zero<<<(M_MSG * 256) / 256, 256>>>(hpk, M_MSG * 256);
    k_pack<<<512, 256>>>(Wz, Wh, Ur, Ow, fnode, fmess, mx);
    k_prep<<<780, 256>>>(emb, Wz, Wh, Wr, Ow, Wzb, Whb, Urb, Ob, EX, EO);

    for (int d = 0; d < DEPTH; d++) {
        // Uh = h @ Ur   (bf16 out)
        TG pU{}; pU.Apk = hpk; pU.Bh = BUh; pU.Bl = BUl; pU.Ub = Ub;
        pU.mT = M_MSG / 128;
        tgemm<0><<<GRID_P, 256, TG_SMEM>>>(pU);
        // gather: sum_h, sum_gh
        k_gather<<<(M_MSG * 64) / 256, 256>>>(mg, hpk, Ub, EX, mx, shp, sgp);
        // z = sigmoid(EXz[mx] + sum_h @ Wzh)   (u16 out)
        TG pZ{}; pZ.Apk = shp; pZ.Bh = BZh; pZ.Bl = BZl; pZ.zu = zu;
        pZ.EX = EX; pZ.mx = mx; pZ.mT = M_MSG / 128;
        tgemm<1><<<GRID_P, 256, TG_SMEM>>>(pZ);
        // h = (1-z)*sum_h + z*tanh(EXh[mx] + sum_gh @ Whh), mask row0
        TG pH{}; pH.Apk = sgp; pH.Bh = BHh; pH.Bl = BHl;
        pH.EX = EX; pH.mx = mx; pH.zu = zu; pH.shp = shp; pH.hpk = hpk;
        pH.mT = M_MSG / 128;
        tgemm<2><<<GRID_P, 256, TG_SMEM>>>(pH);
    }

    // mess_nei per node (packed)
    k_gnode<<<(NNODE * 64) / 256, 256>>>(ng, hpk, mnp);

    // node_vec = relu(EO[fnode] + mn @ Ow2)
    TG pN{}; pN.Apk = mnp; pN.Bh = BOh; pN.Bl = BOl;
    pN.EO = EO; pN.fn = fnode; pN.nv = nv; pN.mT = NNODE / 128;
    tgemm<3><<<GRID_P, 256, TG_SMEM>>>(pN);

    // segment mean (sorted scopes, deterministic)
    k_seg<<<NTREE, 256>>>(scope, nv, out);
}

// round 12
// speedup vs baseline: 2.5082x; 1.0901x over previous
#include <cuda_runtime.h>
#include <cuda_bf16.h>
#include <cstdint>
#include <cstddef>

#define M_MSG 131072
#define NNODE 65536
#define HID   256
#define DEPTH 6
#define NTREE 2048
#define GRID_P 148

#if defined(__CUDA_ARCH_FEAT_SM103_ALL) || defined(__CUDA_ARCH_FEAT_SM100_ALL) || \
    defined(__CUDA_ARCH_FEAT_SM101_ALL) || defined(__CUDA_ARCH_FEAT_SM110_ALL)
#define TC_OK 1
#else
#define TC_OK 0
#endif

// ---------------- static device scratch ------------------------------------
// Per-message record: [0:256) h_hi | [256:512) h_lo | [512:768) U   (bf16)
__device__ __nv_bfloat16 g_rec[(size_t)M_MSG * 768];
// GEMM A operands as bf16 hi/lo planes
__device__ __nv_bfloat16 g_shh[(size_t)M_MSG * 256], g_shl[(size_t)M_MSG * 256]; // sum_h
__device__ __nv_bfloat16 g_sgh[(size_t)M_MSG * 256], g_sgl[(size_t)M_MSG * 256]; // sum_gh
__device__ __nv_bfloat16 g_mnh[(size_t)NNODE * 256], g_mnl[(size_t)NNODE * 256]; // mess_nei
__device__ unsigned short g_zu[(size_t)M_MSG * 256];  // z gate u16 fixed point
__device__ float g_nv[(size_t)NNODE * 256];           // node_vec
__device__ float g_EX[780 * 768];                     // emb@[Wzx|Whx|Wr]+biases
__device__ float g_EO[780 * 256];                     // emb@Ow1+Ob
__device__ int   g_mx[M_MSG];                         // fnode[fmess[m]]
// bf16 hi/lo split weights, [n][k] layout (B operand = W^T), all 256x256
__device__ __nv_bfloat16 g_BUh[256 * 256], g_BUl[256 * 256];  // Ur^T
__device__ __nv_bfloat16 g_BZh[256 * 256], g_BZl[256 * 256];  // Wzh^T
__device__ __nv_bfloat16 g_BHh[256 * 256], g_BHl[256 * 256];  // Whh^T
__device__ __nv_bfloat16 g_BOh[256 * 256], g_BOl[256 * 256];  // Ow2^T

// ---------------- bf16 helpers ----------------------------------------------
__device__ __forceinline__ float bf_lo16(uint32_t u) { return __uint_as_float(u << 16); }
__device__ __forceinline__ float bf_hi16(uint32_t u) { return __uint_as_float(u & 0xFFFF0000u); }
__device__ __forceinline__ uint32_t bf2pk(float a, float b) {
    return (uint32_t)__bfloat16_as_ushort(__float2bfloat16(a))
         | ((uint32_t)__bfloat16_as_ushort(__float2bfloat16(b)) << 16);
}
__device__ __forceinline__ float lo_of(float v) {
    return v - __bfloat162float(__float2bfloat16(v));
}
__device__ __forceinline__ float sgm(float x) { return 1.0f / (1.0f + __expf(-x)); }

// ---------------- PTX helpers ------------------------------------------------
__device__ __forceinline__ uint32_t su32(const void* p) {
    uint32_t a;
    asm("{ .reg .u64 t; cvta.to.shared.u64 t, %1; cvt.u32.u64 %0, t; }"
        : "=r"(a) : "l"(p));
    return a;
}
#if TC_OK
__device__ __forceinline__ bool elect1() {
    uint32_t p;
    asm volatile("{\n\t.reg .pred p;\n\telect.sync _|p, 0xFFFFFFFF;\n\t"
                 "selp.b32 %0, 1, 0, p;\n\t}" : "=r"(p));
    return p != 0;
}
__device__ __forceinline__ void mbar_init(uint32_t a, uint32_t cnt) {
    asm volatile("mbarrier.init.shared.b64 [%0], %1;" :: "r"(a), "r"(cnt) : "memory");
}
__device__ __forceinline__ void mbar_wait(uint32_t a, int par) {
    asm volatile(
        "{\n\t.reg .pred P;\n"
        "W%=:\n\t"
        "mbarrier.try_wait.parity.acquire.cta.shared::cta.b64 P, [%0], %1, 0x989680;\n\t"
        "@P bra.uni D%=;\n\t"
        "bra.uni W%=;\n"
        "D%=:\n\t}" :: "r"(a), "r"(par) : "memory");
}
__device__ __forceinline__ void tc_alloc(uint32_t smem_res, uint32_t ncols) {
    asm volatile("tcgen05.alloc.cta_group::1.sync.aligned.shared::cta.b32 [%0], %1;"
                 :: "r"(smem_res), "r"(ncols) : "memory");
}
__device__ __forceinline__ void tc_dealloc(uint32_t tmem, uint32_t ncols) {
    asm volatile("tcgen05.dealloc.cta_group::1.sync.aligned.b32 %0, %1;"
                 :: "r"(tmem), "r"(ncols));
}
__device__ __forceinline__ void tc_commit(uint32_t mbar) {
    asm volatile("tcgen05.commit.cta_group::1.mbarrier::arrive::one.shared::cluster.b64 [%0];"
                 :: "r"(mbar) : "memory");
}
__device__ __forceinline__ void mma_f16_ss(uint32_t d, uint64_t ad, uint64_t bd,
                                           uint32_t idesc, bool acc) {
    uint32_t en = acc ? 1u : 0u;
    asm volatile(
        "{\n\t.reg .pred p;\n\tsetp.ne.u32 p, %5, 0;\n\t"
        "tcgen05.mma.cta_group::1.kind::f16 [%0], %1, %2, %3, {%4, %4, %4, %4}, p;\n\t}"
        :: "r"(d), "l"(ad), "l"(bd), "r"(idesc), "r"(0u), "r"(en) : "memory");
}
__device__ __forceinline__ void tmem_ld32(uint32_t* r, uint32_t addr) {
    asm volatile(
        "tcgen05.ld.sync.aligned.32x32b.x32.b32 "
        "{%0,%1,%2,%3,%4,%5,%6,%7,%8,%9,%10,%11,%12,%13,%14,%15,"
        "%16,%17,%18,%19,%20,%21,%22,%23,%24,%25,%26,%27,%28,%29,%30,%31}, [%32];"
        : "=r"(r[0]), "=r"(r[1]), "=r"(r[2]), "=r"(r[3]),
          "=r"(r[4]), "=r"(r[5]), "=r"(r[6]), "=r"(r[7]),
          "=r"(r[8]), "=r"(r[9]), "=r"(r[10]), "=r"(r[11]),
          "=r"(r[12]), "=r"(r[13]), "=r"(r[14]), "=r"(r[15]),
          "=r"(r[16]), "=r"(r[17]), "=r"(r[18]), "=r"(r[19]),
          "=r"(r[20]), "=r"(r[21]), "=r"(r[22]), "=r"(r[23]),
          "=r"(r[24]), "=r"(r[25]), "=r"(r[26]), "=r"(r[27]),
          "=r"(r[28]), "=r"(r[29]), "=r"(r[30]), "=r"(r[31])
        : "r"(addr));
}
__device__ __forceinline__ void cp16(uint32_t dst, const void* src) {
    asm volatile("cp.async.cg.shared.global [%0], [%1], 16;"
                 :: "r"(dst), "l"(src) : "memory");
}
#define CP_COMMIT()      asm volatile("cp.async.commit_group;" ::: "memory")
#define CP_WAIT(n)       asm volatile("cp.async.wait_group %0;" :: "n"(n) : "memory")
#define TC_WAIT_LD()      asm volatile("tcgen05.wait::ld.sync.aligned;" ::: "memory")
#define TC_FENCE_AFTER()  asm volatile("tcgen05.fence::after_thread_sync;" ::: "memory")
#define TC_FENCE_BEFORE() asm volatile("tcgen05.fence::before_thread_sync;" ::: "memory")
#define FENCE_ASYNC()     asm volatile("fence.proxy.async.shared::cta;" ::: "memory")
#endif  // TC_OK

#define SWZ(o) ((o) ^ (((o) >> 3) & 0x70))

__device__ __forceinline__ uint64_t mk_desc(uint32_t addr) {
    return (2ull << 61) | (1ull << 46) | (64ull << 32) | (1ull << 16)
         | ((uint64_t)(addr >> 4) & 0x3FFF);
}

// idesc: dtype=F32, a=BF16, b=BF16, N=256, M=128
static constexpr uint32_t IDESC =
    (1u << 4) | (1u << 7) | (1u << 10) | ((256u / 8) << 17) | ((128u / 16) << 24);

// SMEM layout (bytes from 1024-aligned base)
#define OFF_PTR   0
#define OFF_MB    16          // chunk mbars @16,24; tile mbars @32,40
#define OFF_AH(s) (1024 + (s) * 32768)
#define OFF_AL(s) (1024 + (s) * 32768 + 16384)
#define OFF_BH(s) (66560 + (s) * 65536)
#define OFF_BL(s) (66560 + (s) * 65536 + 32768)
#define TG_SMEM   198656

// ---------------- small kernels ---------------------------------------------
__global__ void k_zero(uint32_t* p, size_t n) {
    size_t i = (size_t)blockIdx.x * blockDim.x + threadIdx.x;
    if (i < n) p[i] = 0u;
}

__device__ __forceinline__ void bsplit(float w, __nv_bfloat16* H, __nv_bfloat16* L, int i) {
    __nv_bfloat16 h = __float2bfloat16(w);
    H[i] = h;
    L[i] = __float2bfloat16(w - __bfloat162float(h));
}

__global__ void k_pack(const float* __restrict__ Wz, const float* __restrict__ Wh,
                       const float* __restrict__ Ur, const float* __restrict__ Ow,
                       const int* __restrict__ fnode, const int* __restrict__ fmess,
                       int* __restrict__ mx) {
    int i = blockIdx.x * blockDim.x + threadIdx.x;
    int st = gridDim.x * blockDim.x;
    for (int t = i; t < 256 * 256; t += st) {
        int n = t >> 8, k = t & 255;
        bsplit(Ur[k * 256 + n],         g_BUh, g_BUl, t);
        bsplit(Wz[(256 + k) * 256 + n], g_BZh, g_BZl, t);
        bsplit(Wh[(256 + k) * 256 + n], g_BHh, g_BHl, t);
        bsplit(Ow[(256 + k) * 256 + n], g_BOh, g_BOl, t);
    }
    for (int t = i; t < M_MSG; t += st) mx[t] = fnode[fmess[t]];
}

// EX/EO tables: per-vocab precompute of all x-dependent matmuls.
__global__ void k_prep(const float* __restrict__ emb,
                       const float* __restrict__ Wz, const float* __restrict__ Wh,
                       const float* __restrict__ Wr, const float* __restrict__ Ow,
                       const float* __restrict__ Wzb, const float* __restrict__ Whb,
                       const float* __restrict__ Urb, const float* __restrict__ Ob,
                       float* __restrict__ EX, float* __restrict__ EO) {
    __shared__ float e[256];
    int v = blockIdx.x, j = threadIdx.x;
    e[j] = emb[v * 256 + j];
    __syncthreads();
    float s0 = 0, s1 = 0, s2 = 0, s3 = 0;
#pragma unroll 4
    for (int k = 0; k < 256; k++) {
        float ek = e[k];
        s0 = fmaf(ek, Wz[k * 256 + j], s0);
        s1 = fmaf(ek, Wh[k * 256 + j], s1);
        s2 = fmaf(ek, Wr[k * 256 + j], s2);
        s3 = fmaf(ek, Ow[k * 256 + j], s3);
    }
    EX[v * 768 + j]       = s0 + Wzb[j];
    EX[v * 768 + 256 + j] = s1 + Whb[j];
    EX[v * 768 + 512 + j] = s2 + Urb[j];
    EO[v * 256 + j]       = s3 + Ob[j];
}

// Gather: sum_h, sum_gh from the per-message record (h_hi|h_lo|U). 64 thr/msg.
__global__ void k_gather(const int* __restrict__ mg,
                         const __nv_bfloat16* __restrict__ rec,
                         const float* __restrict__ EX, const int* __restrict__ mx,
                         __nv_bfloat16* __restrict__ shh, __nv_bfloat16* __restrict__ shl,
                         __nv_bfloat16* __restrict__ sgh, __nv_bfloat16* __restrict__ sgl) {
    int gt = blockIdx.x * blockDim.x + threadIdx.x;
    int msg = gt >> 6;
    int j = gt & 63;
    if (msg >= M_MSG) return;
    int mxv = __ldg(mx + msg);
    float4 r1 = *(const float4*)(EX + (size_t)mxv * 768 + 512 + j * 4);
    float sh0 = 0, sh1 = 0, sh2 = 0, sh3 = 0;
    float sg0 = 0, sg1 = 0, sg2 = 0, sg3 = 0;
#pragma unroll
    for (int k = 0; k < 5; k++) {
        int gi = __ldg(mg + msg * 5 + k);
        const __nv_bfloat16* rp = rec + (size_t)gi * 768 + j * 4;
        uint2 hh = *(const uint2*)(rp);
        uint2 hl = *(const uint2*)(rp + 256);
        uint2 uu = *(const uint2*)(rp + 512);
        float h0 = bf_lo16(hh.x) + bf_lo16(hl.x);
        float h1 = bf_hi16(hh.x) + bf_hi16(hl.x);
        float h2 = bf_lo16(hh.y) + bf_lo16(hl.y);
        float h3 = bf_hi16(hh.y) + bf_hi16(hl.y);
        sh0 += h0; sh1 += h1; sh2 += h2; sh3 += h3;
        sg0 += sgm(r1.x + bf_lo16(uu.x)) * h0;
        sg1 += sgm(r1.y + bf_hi16(uu.x)) * h1;
        sg2 += sgm(r1.z + bf_lo16(uu.y)) * h2;
        sg3 += sgm(r1.w + bf_hi16(uu.y)) * h3;
    }
    size_t o = (size_t)msg * 256 + j * 4;
    *(uint2*)(shh + o) = make_uint2(bf2pk(sh0, sh1), bf2pk(sh2, sh3));
    *(uint2*)(shl + o) = make_uint2(bf2pk(lo_of(sh0), lo_of(sh1)), bf2pk(lo_of(sh2), lo_of(sh3)));
    *(uint2*)(sgh + o) = make_uint2(bf2pk(sg0, sg1), bf2pk(sg2, sg3));
    *(uint2*)(sgl + o) = make_uint2(bf2pk(lo_of(sg0), lo_of(sg1)), bf2pk(lo_of(sg2), lo_of(sg3)));
}

// Per-node neighbor-message sum (reads record h planes, writes mn planes).
__global__ void k_gnode(const int* __restrict__ ng,
                        const __nv_bfloat16* __restrict__ rec,
                        __nv_bfloat16* __restrict__ mnh, __nv_bfloat16* __restrict__ mnl) {
    int gt = blockIdx.x * blockDim.x + threadIdx.x;
    int n = gt >> 6;
    int j = gt & 63;
    if (n >= NNODE) return;
    float x = 0, y = 0, z = 0, w = 0;
#pragma unroll
    for (int k = 0; k < 5; k++) {
        int gi = __ldg(ng + n * 5 + k);
        const __nv_bfloat16* rp = rec + (size_t)gi * 768 + j * 4;
        uint2 hh = *(const uint2*)(rp);
        uint2 hl = *(const uint2*)(rp + 256);
        x += bf_lo16(hh.x) + bf_lo16(hl.x);
        y += bf_hi16(hh.x) + bf_hi16(hl.x);
        z += bf_lo16(hh.y) + bf_lo16(hl.y);
        w += bf_hi16(hh.y) + bf_hi16(hl.y);
    }
    size_t o = (size_t)n * 256 + j * 4;
    *(uint2*)(mnh + o) = make_uint2(bf2pk(x, y), bf2pk(z, w));
    *(uint2*)(mnl + o) = make_uint2(bf2pk(lo_of(x), lo_of(y)), bf2pk(lo_of(z), lo_of(w)));
}

// Deterministic segment mean over sorted scope_ids.
__global__ void k_seg(const int* __restrict__ scope, const float* __restrict__ nv,
                      float* __restrict__ out) {
    int t = blockIdx.x;
    int j = threadIdx.x;
    int lo = 0, hi = NNODE;
    while (lo < hi) { int mid = (lo + hi) >> 1; if (scope[mid] < t) lo = mid + 1; else hi = mid; }
    int lo2 = lo, hi2 = NNODE;
    while (lo2 < hi2) { int mid = (lo2 + hi2) >> 1; if (scope[mid] < t + 1) lo2 = mid + 1; else hi2 = mid; }
    float s = 0.f;
    for (int r = lo; r < lo2; r++) s += nv[(size_t)r * HID + j];
    out[(size_t)t * HID + j] = s / fmaxf((float)(lo2 - lo), 1.f);
}

// ---------------- persistent tcgen05 GEMM, 128x256 tile ---------------------
// A = bf16 hi/lo planes (row stride lda elements). All staging via cp.async.
// Single fp32 accumulator D (256 TMEM cols), ping-pong per tile (0 / 256).
// Per K64 chunk: 12 MMAs. Deferred epilogue overlaps next tile's MMAs.
//   MODE 0 (U):  rec[m][512+col] = bf16(v)
//   MODE 1 (Z):  zu = u16(sigmoid(EXz[mx[m]] + v) * 65535)
//   MODE 2 (H):  h = (1-z)*sum_h + z*tanh(EXh[mx[m]] + v); mask row0;
//                write rec h planes (hi @ col, lo @ 256+col)
//   MODE 3 (NV): nv = relu(EO[fn[m]] + v)
struct TG {
    const __nv_bfloat16 *Ah, *Al; int lda;
    const __nv_bfloat16 *Bh, *Bl;      // [256][256]
    __nv_bfloat16* rec;                // MODE 0 / MODE 2 out
    unsigned short* zu;                // MODE 1 out / MODE 2 in
    const float* EX; const int* mx;    // MODE 1,2
    const __nv_bfloat16 *shh, *shl;    // MODE 2 in
    const float* EO; const int* fn; float* nv;  // MODE 3
    int mT;
};

#if TC_OK
template <int MODE>
__device__ __forceinline__ void epi(const TG& p, uint32_t dbase, int m0, int tid) {
    int w = tid >> 5, l = tid & 31;
    int row = (w & 3) * 32 + l;
    int m = m0 + row;
    int chl = (w >> 2) * 128;
    int mxm = 0;
    if (MODE == 1 || MODE == 2) mxm = __ldg(p.mx + m);
    if (MODE == 3) mxm = __ldg(p.fn + m);
#pragma unroll 1
    for (int cb = 0; cb < 4; cb++) {
        int col = chl + cb * 32;
        uint32_t rr[32];
        tmem_ld32(rr, dbase + col);
        TC_WAIT_LD();
        float v[32];
#pragma unroll
        for (int i = 0; i < 32; i++) v[i] = __uint_as_float(rr[i]);
        if (MODE == 0) {
            uint4* dst = (uint4*)(p.rec + (size_t)m * 768 + 512 + col);
#pragma unroll
            for (int i2 = 0; i2 < 4; i2++)
                dst[i2] = make_uint4(bf2pk(v[i2*8+0], v[i2*8+1]), bf2pk(v[i2*8+2], v[i2*8+3]),
                                     bf2pk(v[i2*8+4], v[i2*8+5]), bf2pk(v[i2*8+6], v[i2*8+7]));
        } else if (MODE == 1) {
            const float4* ex4 = (const float4*)(p.EX + (size_t)mxm * 768 + col);
            uint32_t zp[16];
#pragma unroll
            for (int j2 = 0; j2 < 8; j2++) {
                float4 ex = ex4[j2];
                uint32_t a = __float2uint_rn(sgm(ex.x + v[j2*4+0]) * 65535.f);
                uint32_t b = __float2uint_rn(sgm(ex.y + v[j2*4+1]) * 65535.f);
                uint32_t c = __float2uint_rn(sgm(ex.z + v[j2*4+2]) * 65535.f);
                uint32_t d = __float2uint_rn(sgm(ex.w + v[j2*4+3]) * 65535.f);
                zp[j2*2+0] = a | (b << 16);
                zp[j2*2+1] = c | (d << 16);
            }
            uint4* dst = (uint4*)(p.zu + (size_t)m * 256 + col);
#pragma unroll
            for (int i2 = 0; i2 < 4; i2++)
                dst[i2] = make_uint4(zp[i2*4+0], zp[i2*4+1], zp[i2*4+2], zp[i2*4+3]);
        } else if (MODE == 2) {
            const float4* xh4 = (const float4*)(p.EX + (size_t)mxm * 768 + 256 + col);
            const uint4* shh4 = (const uint4*)(p.shh + (size_t)m * 256 + col);
            const uint4* shl4 = (const uint4*)(p.shl + (size_t)m * 256 + col);
            const uint4* zp4 = (const uint4*)(p.zu + (size_t)m * 256 + col);
            uint4* hdh = (uint4*)(p.rec + (size_t)m * 768 + col);
            uint4* hdl = (uint4*)(p.rec + (size_t)m * 768 + 256 + col);
            const float inv = 1.f / 65535.f;
#pragma unroll
            for (int j2 = 0; j2 < 4; j2++) {     // 8-col groups
                float4 xa = xh4[j2 * 2], xb = xh4[j2 * 2 + 1];
                uint4 sh = shh4[j2], sl = shl4[j2], zz = zp4[j2];
                float xh[8] = {xa.x, xa.y, xa.z, xa.w, xb.x, xb.y, xb.z, xb.w};
                float su[8] = {bf_lo16(sh.x) + bf_lo16(sl.x), bf_hi16(sh.x) + bf_hi16(sl.x),
                               bf_lo16(sh.y) + bf_lo16(sl.y), bf_hi16(sh.y) + bf_hi16(sl.y),
                               bf_lo16(sh.z) + bf_lo16(sl.z), bf_hi16(sh.z) + bf_hi16(sl.z),
                               bf_lo16(sh.w) + bf_lo16(sl.w), bf_hi16(sh.w) + bf_hi16(sl.w)};
                uint32_t zw[4] = {zz.x, zz.y, zz.z, zz.w};
                float h[8];
#pragma unroll
                for (int i = 0; i < 8; i++) {
                    float z = (float)((zw[i >> 1] >> ((i & 1) * 16)) & 0xFFFF) * inv;
                    h[i] = (1.f - z) * su[i] + z * tanhf(xh[i] + v[j2 * 8 + i]);
                    if (m == 0) h[i] = 0.f;
                }
                hdh[j2] = make_uint4(bf2pk(h[0], h[1]), bf2pk(h[2], h[3]),
                                     bf2pk(h[4], h[5]), bf2pk(h[6], h[7]));
                hdl[j2] = make_uint4(bf2pk(lo_of(h[0]), lo_of(h[1])), bf2pk(lo_of(h[2]), lo_of(h[3])),
                                     bf2pk(lo_of(h[4]), lo_of(h[5])), bf2pk(lo_of(h[6]), lo_of(h[7])));
            }
        } else {
            const float4* eo4 = (const float4*)(p.EO + (size_t)mxm * 256 + col);
            float4* dst = (float4*)(p.nv + (size_t)m * 256 + col);
#pragma unroll
            for (int j2 = 0; j2 < 8; j2++) {
                float4 eo = eo4[j2];
                dst[j2] = make_float4(fmaxf(eo.x + v[j2*4+0], 0.f),
                                      fmaxf(eo.y + v[j2*4+1], 0.f),
                                      fmaxf(eo.z + v[j2*4+2], 0.f),
                                      fmaxf(eo.w + v[j2*4+3], 0.f));
            }
        }
    }
    TC_FENCE_BEFORE();
}
#endif

template <int MODE>
__global__ void __launch_bounds__(256) tgemm(TG p) {
    extern __shared__ char smraw[];
    char* sm = (char*)(((uintptr_t)smraw + 1023) & ~(uintptr_t)1023);
    const int tid = threadIdx.x;
#if TC_OK
    uint32_t sb = su32(sm);
    if (tid < 32) tc_alloc(sb + OFF_PTR, 512);
    if (tid == 0) {
        mbar_init(sb + OFF_MB + 0, 1);  mbar_init(sb + OFF_MB + 8, 1);
        mbar_init(sb + OFF_MB + 16, 1); mbar_init(sb + OFF_MB + 24, 1);
    }
    __syncthreads();
    uint32_t tmem = *(const uint32_t*)(sm + OFF_PTR);

    const int q = tid & 7, r8 = tid >> 3;   // A: 4 rows x 2 planes; B: 8 rows x 2

    int ph0 = 0, ph1 = 0, pend0 = 0, pend1 = 0;
    int tp0 = 0, tp1 = 0;
    int prev_m0 = -1, prev_db = 0;
    int lc = 0;

    for (int ti = blockIdx.x; ti < p.mT; ti += gridDim.x, lc++) {
        int m0 = ti * 128;
        int db = lc & 1;
        for (int c = 0; c < 4; c++) {
            int s = c & 1;
            if (s == 0) { if (pend0) { mbar_wait(sb + OFF_MB + 0, ph0); ph0 ^= 1; pend0 = 0; } }
            else        { if (pend1) { mbar_wait(sb + OFF_MB + 8, ph1); ph1 ^= 1; pend1 = 0; } }
            // A chunk via cp.async: hi/lo planes, 128 rows x 128B, SW128
            {
                const __nv_bfloat16* Ah = p.Ah + (size_t)m0 * p.lda + c * 64 + q * 8;
                const __nv_bfloat16* Al = p.Al + (size_t)m0 * p.lda + c * 64 + q * 8;
#pragma unroll
                for (int u = 0; u < 4; u++) {
                    int row = u * 32 + r8;
                    uint32_t sw = SWZ((uint32_t)(row * 128 + q * 16));
                    cp16(sb + OFF_AH(s) + sw, Ah + (size_t)row * p.lda);
                    cp16(sb + OFF_AL(s) + sw, Al + (size_t)row * p.lda);
                }
            }
            // B chunk via cp.async
            {
                const __nv_bfloat16* Bh = p.Bh + c * 64 + q * 8;
                const __nv_bfloat16* Bl = p.Bl + c * 64 + q * 8;
#pragma unroll
                for (int u = 0; u < 8; u++) {
                    int row = u * 32 + r8;
                    uint32_t sw = SWZ((uint32_t)(row * 128 + q * 16));
                    cp16(sb + OFF_BH(s) + sw, Bh + (size_t)row * 256);
                    cp16(sb + OFF_BL(s) + sw, Bl + (size_t)row * 256);
                }
            }
            CP_COMMIT();
            if (c >= 1) {
                CP_WAIT(1);
                __syncthreads();
                FENCE_ASYNC();
                int sp = s ^ 1;   // buffer of chunk c-1
                if (tid < 32 && elect1()) {
                    uint64_t ah = mk_desc(sb + OFF_AH(sp));
                    uint64_t al = mk_desc(sb + OFF_AL(sp));
                    uint64_t bh = mk_desc(sb + OFF_BH(sp));
                    uint64_t bl = mk_desc(sb + OFF_BL(sp));
                    uint32_t d = tmem + db * 256;
#pragma unroll
                    for (int k = 0; k < 4; k++) {
                        bool acc = (c > 1) || (k > 0);
                        mma_f16_ss(d, ah + k * 2, bh + k * 2, IDESC, acc);
                        mma_f16_ss(d, al + k * 2, bh + k * 2, IDESC, true);
                        mma_f16_ss(d, ah + k * 2, bl + k * 2, IDESC, true);
                    }
                    tc_commit(sb + OFF_MB + sp * 8);
                }
                if (sp) pend1 = 1; else pend0 = 1;
            }
        }
        // tail: MMA of chunk 3 (buffer 1)
        CP_WAIT(0);
        __syncthreads();
        FENCE_ASYNC();
        if (tid < 32 && elect1()) {
            uint64_t ah = mk_desc(sb + OFF_AH(1));
            uint64_t al = mk_desc(sb + OFF_AL(1));
            uint64_t bh = mk_desc(sb + OFF_BH(1));
            uint64_t bl = mk_desc(sb + OFF_BL(1));
            uint32_t d = tmem + db * 256;
#pragma unroll
            for (int k = 0; k < 4; k++) {
                mma_f16_ss(d, ah + k * 2, bh + k * 2, IDESC, true);
                mma_f16_ss(d, al + k * 2, bh + k * 2, IDESC, true);
                mma_f16_ss(d, ah + k * 2, bl + k * 2, IDESC, true);
            }
            tc_commit(sb + OFF_MB + 8);
            tc_commit(sb + OFF_MB + 16 + db * 8);
        }
        pend1 = 1;
        // deferred epilogue of previous tile (overlaps this tile's MMAs)
        if (prev_m0 >= 0) {
            if (prev_db == 0) { mbar_wait(sb + OFF_MB + 16, tp0); tp0 ^= 1; }
            else              { mbar_wait(sb + OFF_MB + 24, tp1); tp1 ^= 1; }
            TC_FENCE_AFTER();
            epi<MODE>(p, tmem + prev_db * 256, prev_m0, tid);
        }
        prev_m0 = m0; prev_db = db;
    }
    if (prev_m0 >= 0) {
        if (prev_db == 0) { mbar_wait(sb + OFF_MB + 16, tp0); tp0 ^= 1; }
        else              { mbar_wait(sb + OFF_MB + 24, tp1); tp1 ^= 1; }
        TC_FENCE_AFTER();
        epi<MODE>(p, tmem + prev_db * 256, prev_m0, tid);
    }
    __syncthreads();
    if (tid < 32) tc_dealloc(tmem, 512);
#else
    // Compile-only fallback for the plain compute_103 PTX pass (never run:
    // exact sm_103a SASS is embedded in the fatbin and always preferred).
    for (int ti = blockIdx.x; ti < p.mT; ti += gridDim.x) {
        int m0 = ti * 128;
        for (int e = tid; e < 128 * 256; e += 256) {
            int r = e >> 8, col = e & 255;
            int m = m0 + r;
            float acc = 0.f;
            for (int k = 0; k < 256; k++) {
                float a = __bfloat162float(p.Ah[(size_t)m * p.lda + k])
                        + __bfloat162float(p.Al[(size_t)m * p.lda + k]);
                float b = __bfloat162float(p.Bh[(size_t)col * 256 + k])
                        + __bfloat162float(p.Bl[(size_t)col * 256 + k]);
                acc += a * b;
            }
            if (MODE == 0) {
                p.rec[(size_t)m * 768 + 512 + col] = __float2bfloat16(acc);
            } else if (MODE == 1) {
                int mxm = p.mx[m];
                float z = sgm(p.EX[(size_t)mxm * 768 + col] + acc);
                p.zu[(size_t)m * 256 + col] =
                    (unsigned short)__float2uint_rn(z * 65535.f);
            } else if (MODE == 2) {
                int mxm = p.mx[m];
                float z = (float)p.zu[(size_t)m * 256 + col] * (1.f / 65535.f);
                float sh = __bfloat162float(p.shh[(size_t)m * 256 + col])
                         + __bfloat162float(p.shl[(size_t)m * 256 + col]);
                float h = (1.f - z) * sh
                        + z * tanhf(p.EX[(size_t)mxm * 768 + 256 + col] + acc);
                if (m == 0) h = 0.f;
                __nv_bfloat16 hb = __float2bfloat16(h);
                p.rec[(size_t)m * 768 + col] = hb;
                p.rec[(size_t)m * 768 + 256 + col] =
                    __float2bfloat16(h - __bfloat162float(hb));
            } else {
                int fn = p.fn[m];
                p.nv[(size_t)m * 256 + col] =
                    fmaxf(p.EO[(size_t)fn * 256 + col] + acc, 0.f);
            }
        }
    }
#endif
}

// ---------------- orchestration --------------------------------------------
extern "C" void kernel_launch(void* const* d_in, const int* in_sizes, int n_in,
                              void* d_out, int out_size) {
    const int*   fnode = (const int*)d_in[0];
    const int*   fmess = (const int*)d_in[1];
    const int*   ng    = (const int*)d_in[2];
    const int*   mg    = (const int*)d_in[3];
    const int*   scope = (const int*)d_in[4];
    const float* emb   = (const float*)d_in[5];
    const float* Wz    = (const float*)d_in[6];
    const float* Wzb   = (const float*)d_in[7];
    const float* Wr    = (const float*)d_in[8];
    const float* Ur    = (const float*)d_in[9];
    const float* Urb   = (const float*)d_in[10];
    const float* Wh    = (const float*)d_in[11];
    const float* Whb   = (const float*)d_in[12];
    const float* Ow    = (const float*)d_in[13];
    const float* Ob    = (const float*)d_in[14];
    float* out = (float*)d_out;

    __nv_bfloat16 *rec, *shh, *shl, *sgh, *sgl, *mnh, *mnl;
    __nv_bfloat16 *BUh, *BUl, *BZh, *BZl, *BHh, *BHl, *BOh, *BOl;
    unsigned short* zu;
    float *nv, *EX, *EO;
    int* mx;
    cudaGetSymbolAddress((void**)&rec, g_rec);
    cudaGetSymbolAddress((void**)&shh, g_shh); cudaGetSymbolAddress((void**)&shl, g_shl);
    cudaGetSymbolAddress((void**)&sgh, g_sgh); cudaGetSymbolAddress((void**)&sgl, g_sgl);
    cudaGetSymbolAddress((void**)&mnh, g_mnh); cudaGetSymbolAddress((void**)&mnl, g_mnl);
    cudaGetSymbolAddress((void**)&zu,  g_zu);
    cudaGetSymbolAddress((void**)&nv,  g_nv);
    cudaGetSymbolAddress((void**)&EX,  g_EX);
    cudaGetSymbolAddress((void**)&EO,  g_EO);
    cudaGetSymbolAddress((void**)&mx,  g_mx);
    cudaGetSymbolAddress((void**)&BUh, g_BUh); cudaGetSymbolAddress((void**)&BUl, g_BUl);
    cudaGetSymbolAddress((void**)&BZh, g_BZh); cudaGetSymbolAddress((void**)&BZl, g_BZl);
    cudaGetSymbolAddress((void**)&BHh, g_BHh); cudaGetSymbolAddress((void**)&BHl, g_BHl);
    cudaGetSymbolAddress((void**)&BOh, g_BOh); cudaGetSymbolAddress((void**)&BOl, g_BOl);

    cudaFuncSetAttribute(tgemm<0>, cudaFuncAttributeMaxDynamicSharedMemorySize, TG_SMEM);
    cudaFuncSetAttribute(tgemm<1>, cudaFuncAttributeMaxDynamicSharedMemorySize, TG_SMEM);
    cudaFuncSetAttribute(tgemm<2>, cudaFuncAttributeMaxDynamicSharedMemorySize, TG_SMEM);
    cudaFuncSetAttribute(tgemm<3>, cudaFuncAttributeMaxDynamicSharedMemorySize, TG_SMEM);

    size_t recw = (size_t)M_MSG * 768 * 2 / 4;
    k_zero<<<(unsigned)((recw + 255) / 256), 256>>>((uint32_t*)rec, recw);
    k_pack<<<512, 256>>>(Wz, Wh, Ur, Ow, fnode, fmess, mx);
    k_prep<<<780, 256>>>(emb, Wz, Wh, Wr, Ow, Wzb, Whb, Urb, Ob, EX, EO);

    for (int d = 0; d < DEPTH; d++) {
        // U = h @ Ur  -> rec[:,512:768]
        TG pU{}; pU.Ah = rec; pU.Al = rec + 256; pU.lda = 768;
        pU.Bh = BUh; pU.Bl = BUl; pU.rec = rec; pU.mT = M_MSG / 128;
        tgemm<0><<<GRID_P, 256, TG_SMEM>>>(pU);
        // gather: sum_h, sum_gh
        k_gather<<<(M_MSG * 64) / 256, 256>>>(mg, rec, EX, mx, shh, shl, sgh, sgl);
        // z = sigmoid(EXz[mx] + sum_h @ Wzh)
        TG pZ{}; pZ.Ah = shh; pZ.Al = shl; pZ.lda = 256;
        pZ.Bh = BZh; pZ.Bl = BZl; pZ.zu = zu; pZ.EX = EX; pZ.mx = mx;
        pZ.mT = M_MSG / 128;
        tgemm<1><<<GRID_P, 256, TG_SMEM>>>(pZ);
        // h = (1-z)*sum_h + z*tanh(EXh[mx] + sum_gh @ Whh) -> rec h planes
        TG pH{}; pH.Ah = sgh; pH.Al = sgl; pH.lda = 256;
        pH.Bh = BHh; pH.Bl = BHl; pH.rec = rec; pH.zu = zu;
        pH.EX = EX; pH.mx = mx; pH.shh = shh; pH.shl = shl;
        pH.mT = M_MSG / 128;
        tgemm<2><<<GRID_P, 256, TG_SMEM>>>(pH);
    }

    // mess_nei per node
    k_gnode<<<(NNODE * 64) / 256, 256>>>(ng, rec, mnh, mnl);

    // node_vec = relu(EO[fnode] + mn @ Ow2)
    TG pN{}; pN.Ah = mnh; pN.Al = mnl; pN.lda = 256;
    pN.Bh = BOh; pN.Bl = BOl; pN.EO = EO; pN.fn = fnode; pN.nv = nv;
    pN.mT = NNODE / 128;
    tgemm<3><<<GRID_P, 256, TG_SMEM>>>(pN);

    // segment mean (sorted scopes, deterministic)
    k_seg<<<NTREE, 256>>>(scope, nv, out);
}